// round 1
// baseline (speedup 1.0000x reference)
#include <cuda_runtime.h>
#include <cuda_bf16.h>
#include <math.h>

#define NTOK 32768        // B*T
#define HD   160          // hidden = embed
#define NV   16           // variables
#define TM   32           // token tile
#define SPAD 33           // smem pad

static __device__ float g_tr[(size_t)NTOK * HD * NV];   // transformed, layout [n][v][h]
static __device__ float g_ctx[64 * HD];                  // additional_context @ Wc

__device__ __forceinline__ float eluf(float x) { return x > 0.f ? x : expm1f(x); }
__device__ __forceinline__ float sigf(float x) { return 1.f / (1.f + expf(-x)); }

extern __shared__ float smem[];

// load one [32 x 160] weight k-tile into smem (coalesced)
__device__ __forceinline__ void load_wtile(float* sW, const float* __restrict__ W,
                                           int kt, int tid) {
#pragma unroll
    for (int t = 0; t < 20; ++t) {
        int l = tid + t * 256;
        int j = l % HD, kk = l / HD;
        sW[kk * HD + j] = W[(size_t)(kt * 32 + kk) * HD + j];
    }
}

// acc[4][5] += K-slab(sK transposed [k][m], pad 33) @ sW tile
__device__ __forceinline__ void gemm_step(const float* sK, const float* sW,
                                          float acc[4][5], int kt, int r, int c) {
#pragma unroll
    for (int kk = 0; kk < 32; ++kk) {
        const float* xk = sK + (kt * 32 + kk) * SPAD + r;
        float a0 = xk[0], a1 = xk[8], a2 = xk[16], a3 = xk[24];
        const float* wk = sW + kk * HD + c;
#pragma unroll
        for (int ji = 0; ji < 5; ++ji) {
            float w = wk[32 * ji];
            acc[0][ji] = fmaf(a0, w, acc[0][ji]);
            acc[1][ji] = fmaf(a1, w, acc[1][ji]);
            acc[2][ji] = fmaf(a2, w, acc[2][ji]);
            acc[3][ji] = fmaf(a3, w, acc[3][ji]);
        }
    }
}

__device__ __forceinline__ void gemm160(const float* sK, const float* __restrict__ W,
                                        float* sW, float acc[4][5], int r, int c, int tid) {
    for (int kt = 0; kt < 5; ++kt) {
        load_wtile(sW, W, kt, tid);
        __syncthreads();
        gemm_step(sK, sW, acc, kt, r, c);
        __syncthreads();
    }
}

// ---------------- kernel 0: ctx = additional_context @ Wc ----------------
__global__ void ctx_kernel(const float* __restrict__ ac, const float* __restrict__ Wc) {
    int b = blockIdx.x, j = threadIdx.x;    // 160 threads
    float s = 0.f;
    for (int k = 0; k < HD; ++k)
        s = fmaf(ac[b * HD + k], Wc[k * HD + j], s);
    g_ctx[b * HD + j] = s;
}

// ---------------- stage A: per-variable GRNs -> g_tr[n][v][h] ----------------
__global__ void __launch_bounds__(256, 2) stageA_kernel(
    const float* __restrict__ emb,
    const float* __restrict__ W1, const float* __restrict__ b1,
    const float* __restrict__ W2, const float* __restrict__ b2,
    const float* __restrict__ Wg, const float* __restrict__ bg,
    const float* __restrict__ Wv, const float* __restrict__ bv,
    const float* __restrict__ lns, const float* __restrict__ lnb)
{
    float* s_x  = smem;                 // [160][33]  x transposed (kept: skip + GEMM1 K-op)
    float* s_h1 = s_x  + HD * SPAD;     // [160][33]
    float* s_h2 = s_h1 + HD * SPAD;     // [160][33]
    float* s_wa = s_h2 + HD * SPAD;     // [32][160]
    float* s_wb = s_wa + 32 * HD;       // [32][160]

    const int v   = blockIdx.x;
    const int n0  = blockIdx.y * TM;
    const int tid = threadIdx.x;
    const int r   = tid >> 5;           // warp id = token group
    const int c   = tid & 31;           // lane    = column group

    // load x tile transposed: s_x[e][m] = emb[n0+m, e, v]
    for (int l = tid; l < HD * TM; l += 256) {
        int e = l % HD, m = l / HD;
        s_x[e * SPAD + m] = emb[(size_t)(n0 + m) * (HD * NV) + (size_t)e * NV + v];
    }
    __syncthreads();

    float acc[4][5];
#pragma unroll
    for (int i = 0; i < 4; ++i)
#pragma unroll
        for (int j = 0; j < 5; ++j) acc[i][j] = 0.f;

    // h1 = elu(x @ W1 + b1)
    gemm160(s_x, W1 + (size_t)v * HD * HD, s_wa, acc, r, c, tid);
#pragma unroll
    for (int mi = 0; mi < 4; ++mi)
#pragma unroll
        for (int ji = 0; ji < 5; ++ji) {
            int j = c + 32 * ji;
            s_h1[j * SPAD + r + 8 * mi] = eluf(acc[mi][ji] + b1[v * HD + j]);
        }
    __syncthreads();

    // h2 = h1 @ W2 + b2
#pragma unroll
    for (int i = 0; i < 4; ++i)
#pragma unroll
        for (int j = 0; j < 5; ++j) acc[i][j] = 0.f;
    gemm160(s_h1, W2 + (size_t)v * HD * HD, s_wa, acc, r, c, tid);
#pragma unroll
    for (int mi = 0; mi < 4; ++mi)
#pragma unroll
        for (int ji = 0; ji < 5; ++ji) {
            int j = c + 32 * ji;
            s_h2[j * SPAD + r + 8 * mi] = acc[mi][ji] + b2[v * HD + j];
        }
    __syncthreads();

    // gate = sigmoid(h2@Wg+bg); val = h2@Wv+bv  (dual GEMM)
    float ag[4][5], av[4][5];
#pragma unroll
    for (int i = 0; i < 4; ++i)
#pragma unroll
        for (int j = 0; j < 5; ++j) { ag[i][j] = 0.f; av[i][j] = 0.f; }

    const float* Wgp = Wg + (size_t)v * HD * HD;
    const float* Wvp = Wv + (size_t)v * HD * HD;
    for (int kt = 0; kt < 5; ++kt) {
        load_wtile(s_wa, Wgp, kt, tid);
        load_wtile(s_wb, Wvp, kt, tid);
        __syncthreads();
#pragma unroll
        for (int kk = 0; kk < 32; ++kk) {
            const float* xk = s_h2 + (kt * 32 + kk) * SPAD + r;
            float a0 = xk[0], a1 = xk[8], a2 = xk[16], a3 = xk[24];
            const float* wg = s_wa + kk * HD + c;
            const float* wv = s_wb + kk * HD + c;
#pragma unroll
            for (int ji = 0; ji < 5; ++ji) {
                float wgx = wg[32 * ji];
                float wvx = wv[32 * ji];
                ag[0][ji] = fmaf(a0, wgx, ag[0][ji]);
                ag[1][ji] = fmaf(a1, wgx, ag[1][ji]);
                ag[2][ji] = fmaf(a2, wgx, ag[2][ji]);
                ag[3][ji] = fmaf(a3, wgx, ag[3][ji]);
                av[0][ji] = fmaf(a0, wvx, av[0][ji]);
                av[1][ji] = fmaf(a1, wvx, av[1][ji]);
                av[2][ji] = fmaf(a2, wvx, av[2][ji]);
                av[3][ji] = fmaf(a3, wvx, av[3][ji]);
            }
        }
        __syncthreads();
    }

    // y = x + sigmoid(ag+bg)*(av+bv);  LayerNorm over H per token;  store [n][v][h]
#pragma unroll
    for (int mi = 0; mi < 4; ++mi) {
#pragma unroll
        for (int ji = 0; ji < 5; ++ji) {
            int j = c + 32 * ji;
            float g  = sigf(ag[mi][ji] + bg[v * HD + j]);
            float vv = av[mi][ji] + bv[v * HD + j];
            ag[mi][ji] = s_x[j * SPAD + r + 8 * mi] + g * vv;   // reuse ag as y
        }
        float s = 0.f, q = 0.f;
#pragma unroll
        for (int ji = 0; ji < 5; ++ji) { float yv = ag[mi][ji]; s += yv; q += yv * yv; }
#pragma unroll
        for (int off = 16; off; off >>= 1) {
            s += __shfl_xor_sync(0xffffffffu, s, off);
            q += __shfl_xor_sync(0xffffffffu, q, off);
        }
        float mean = s * (1.f / HD);
        float var  = q * (1.f / HD) - mean * mean;
        float rstd = rsqrtf(var + 1e-5f);
        int m = r + 8 * mi;
        float* orow = g_tr + (size_t)(n0 + m) * (HD * NV) + (size_t)v * HD;
#pragma unroll
        for (int ji = 0; ji < 5; ++ji) {
            int j = c + 32 * ji;
            orow[j] = (ag[mi][ji] - mean) * rstd * lns[v * HD + j] + lnb[v * HD + j];
        }
    }
}

// ---------------- stage B: flattened GRN + softmax ----------------
__global__ void __launch_bounds__(256, 2) stageB_kernel(
    const float* __restrict__ Wskip, const float* __restrict__ bskip,
    const float* __restrict__ W1,    const float* __restrict__ b1,
    const float* __restrict__ W2,    const float* __restrict__ b2,
    const float* __restrict__ Wg,    const float* __restrict__ bg,
    const float* __restrict__ Wv,    const float* __restrict__ bv,
    const float* __restrict__ lns,   const float* __restrict__ lnb,
    float* __restrict__ out_sw, float* __restrict__ out_sg)
{
    float* s_h2 = smem;                  // [160][33]
    float* s_h3 = s_h2 + HD * SPAD;      // [160][33]
    float* s_w  = s_h3 + HD * SPAD;      // [32][160]
    float* s_f  = s_w  + 32 * HD;        // [32][33]  flat k-tile transposed
    float* s_sk = s_f  + 32 * SPAD;      // [32][16]
    float* s_gv = s_sk + 32 * 16;        // [160][32] Wg|Wv fused

    const int n0  = blockIdx.x * TM;
    const int tid = threadIdx.x;
    const int r   = tid >> 5;
    const int c   = tid & 31;
    const int bidx = n0 >> 9;            // batch index (512 tokens per batch, tile-aligned)

    float acc[4][5];
    float asx[4] = {0.f, 0.f, 0.f, 0.f};
#pragma unroll
    for (int i = 0; i < 4; ++i)
#pragma unroll
        for (int j = 0; j < 5; ++j) acc[i][j] = 0.f;

    // big GEMM: flat[2560] -> (W1:160 | Wskip:16). g_tr is [n][v][h]; the
    // reference flatten index is h*V+v, so permute the weight ROW instead.
    for (int kt = 0; kt < 80; ++kt) {
        int k0 = kt * 32;
#pragma unroll
        for (int t = 0; t < 4; ++t) {          // flat tile (coalesced in k)
            int l = tid + t * 256;
            int kk = l & 31, m = l >> 5;
            s_f[kk * SPAD + m] = g_tr[(size_t)(n0 + m) * (HD * NV) + k0 + kk];
        }
#pragma unroll
        for (int t = 0; t < 20; ++t) {         // W1 tile, permuted rows
            int l = tid + t * 256;
            int j = l % HD, kk = l / HD;
            int k = k0 + kk;
            int pk = (k % HD) * NV + (k / HD);
            s_w[kk * HD + j] = W1[(size_t)pk * HD + j];
        }
#pragma unroll
        for (int t = 0; t < 2; ++t) {          // Wskip tile, permuted rows
            int l = tid + t * 256;
            int kk = l >> 4, vv = l & 15;
            int k = k0 + kk;
            int pk = (k % HD) * NV + (k / HD);
            s_sk[kk * NV + vv] = Wskip[(size_t)pk * NV + vv];
        }
        __syncthreads();
#pragma unroll
        for (int kk = 0; kk < 32; ++kk) {
            const float* fk = s_f + kk * SPAD + r;
            float a0 = fk[0], a1 = fk[8], a2 = fk[16], a3 = fk[24];
            const float* wk = s_w + kk * HD + c;
#pragma unroll
            for (int ji = 0; ji < 5; ++ji) {
                float w = wk[32 * ji];
                acc[0][ji] = fmaf(a0, w, acc[0][ji]);
                acc[1][ji] = fmaf(a1, w, acc[1][ji]);
                acc[2][ji] = fmaf(a2, w, acc[2][ji]);
                acc[3][ji] = fmaf(a3, w, acc[3][ji]);
            }
            if (c < NV) {
                float ws = s_sk[kk * NV + c];
                asx[0] = fmaf(a0, ws, asx[0]);
                asx[1] = fmaf(a1, ws, asx[1]);
                asx[2] = fmaf(a2, ws, asx[2]);
                asx[3] = fmaf(a3, ws, asx[3]);
            }
        }
        __syncthreads();
    }

    // h2 = elu(acc + b1 + ctx[b])
#pragma unroll
    for (int mi = 0; mi < 4; ++mi)
#pragma unroll
        for (int ji = 0; ji < 5; ++ji) {
            int j = c + 32 * ji;
            s_h2[j * SPAD + r + 8 * mi] = eluf(acc[mi][ji] + b1[j] + g_ctx[bidx * HD + j]);
        }
    __syncthreads();

    // h3 = h2 @ W2 + b2
#pragma unroll
    for (int i = 0; i < 4; ++i)
#pragma unroll
        for (int j = 0; j < 5; ++j) acc[i][j] = 0.f;
    gemm160(s_h2, W2, s_w, acc, r, c, tid);
#pragma unroll
    for (int mi = 0; mi < 4; ++mi)
#pragma unroll
        for (int ji = 0; ji < 5; ++ji) {
            int j = c + 32 * ji;
            s_h3[j * SPAD + r + 8 * mi] = acc[mi][ji] + b2[j];
        }
#pragma unroll
    for (int t = 0; t < 20; ++t) {            // fused Wg|Wv [160][32]
        int l = tid + t * 256;
        int cc = l & 31, k = l >> 5;
        s_gv[k * 32 + cc] = (cc < NV) ? Wg[k * NV + cc] : Wv[k * NV + (cc - NV)];
    }
    __syncthreads();

    // lane c<16: gate col c; lane c>=16: value col c-16
    float gv[4] = {0.f, 0.f, 0.f, 0.f};
#pragma unroll 8
    for (int k = 0; k < HD; ++k) {
        float w = s_gv[k * 32 + c];
        gv[0] = fmaf(s_h3[k * SPAD + r],      w, gv[0]);
        gv[1] = fmaf(s_h3[k * SPAD + r + 8],  w, gv[1]);
        gv[2] = fmaf(s_h3[k * SPAD + r + 16], w, gv[2]);
        gv[3] = fmaf(s_h3[k * SPAD + r + 24], w, gv[3]);
    }

    int vc = c & 15;
    float bgv = (c < NV) ? bg[vc] : bv[vc];
    float skb = bskip[vc];
    float lsc = lns[vc], lbc = lnb[vc];
#pragma unroll
    for (int mi = 0; mi < 4; ++mi) {
        float z = gv[mi] + bgv;
        float gval = (c < NV) ? sigf(z) : z;                 // gate | value
        float partner = __shfl_xor_sync(0xffffffffu, gval, 16);
        float y = asx[mi] + skb + gval * partner;            // skip + glu2 (valid c<16)
        float s = y, q = y * y;
#pragma unroll
        for (int off = 8; off; off >>= 1) {                  // LN over 16 (half-warp)
            s += __shfl_xor_sync(0xffffffffu, s, off);
            q += __shfl_xor_sync(0xffffffffu, q, off);
        }
        float mean = s * (1.f / 16.f);
        float var  = q * (1.f / 16.f) - mean * mean;
        float rstd = rsqrtf(var + 1e-5f);
        float logit = (y - mean) * rstd * lsc + lbc;
        float mx = logit;
#pragma unroll
        for (int off = 8; off; off >>= 1)
            mx = fmaxf(mx, __shfl_xor_sync(0xffffffffu, mx, off));
        float e = expf(logit - mx);
        float se = e;
#pragma unroll
        for (int off = 8; off; off >>= 1)
            se += __shfl_xor_sync(0xffffffffu, se, off);
        if (c < NV) {
            int n = n0 + r + 8 * mi;
            out_sw[(size_t)n * NV + c] = e / se;
            out_sg[(size_t)n * NV + c] = gval;
        }
    }
}

// ---------------- stage C: temporal_ctx[n][h] = sum_v tr[n][v][h] * w[n][v] ----------------
__global__ void __launch_bounds__(256) stageC_kernel(const float* __restrict__ sw,
                                                     float* __restrict__ out_tc) {
    __shared__ float s_w[16 * NV];
    int n0 = blockIdx.x * 16;
    int tid = threadIdx.x;
    s_w[tid] = sw[(size_t)n0 * NV + tid];
    __syncthreads();
#pragma unroll
    for (int t = 0; t < 10; ++t) {
        int l = tid + t * 256;
        int h = l % HD, m = l / HD;
        const float* row = g_tr + (size_t)(n0 + m) * (HD * NV) + h;
        float s = 0.f;
#pragma unroll
        for (int vv = 0; vv < NV; ++vv)
            s = fmaf(row[vv * HD], s_w[m * NV + vv], s);
        out_tc[(size_t)(n0 + m) * HD + h] = s;
    }
}

extern "C" void kernel_launch(void* const* d_in, const int* in_sizes, int n_in,
                              void* d_out, int out_size)
{
    const float* emb   = (const float*)d_in[0];
    const float* ac    = (const float*)d_in[1];
    const float* sv_W1 = (const float*)d_in[2];
    const float* sv_b1 = (const float*)d_in[3];
    const float* sv_W2 = (const float*)d_in[4];
    const float* sv_b2 = (const float*)d_in[5];
    const float* sv_Wg = (const float*)d_in[6];
    const float* sv_bg = (const float*)d_in[7];
    const float* sv_Wv = (const float*)d_in[8];
    const float* sv_bv = (const float*)d_in[9];
    const float* sv_ls = (const float*)d_in[10];
    const float* sv_lb = (const float*)d_in[11];
    const float* fWsk  = (const float*)d_in[12];
    const float* fbsk  = (const float*)d_in[13];
    const float* fW1   = (const float*)d_in[14];
    const float* fb1   = (const float*)d_in[15];
    const float* fWc   = (const float*)d_in[16];
    const float* fW2   = (const float*)d_in[17];
    const float* fb2   = (const float*)d_in[18];
    const float* fWg   = (const float*)d_in[19];
    const float* fbg   = (const float*)d_in[20];
    const float* fWv   = (const float*)d_in[21];
    const float* fbv   = (const float*)d_in[22];
    const float* fls   = (const float*)d_in[23];
    const float* flb   = (const float*)d_in[24];

    float* out    = (float*)d_out;
    float* out_tc = out;                              // [BT,160]
    float* out_sw = out + (size_t)NTOK * HD;          // [BT,16]
    float* out_sg = out_sw + (size_t)NTOK * NV;       // [BT,16]

    const int SMEM_A = (3 * HD * SPAD + 2 * 32 * HD) * (int)sizeof(float);   // 104320
    const int SMEM_B = (2 * HD * SPAD + 32 * HD + 32 * SPAD + 32 * 16 + HD * 32) * (int)sizeof(float); // 89472
    cudaFuncSetAttribute(stageA_kernel, cudaFuncAttributeMaxDynamicSharedMemorySize, SMEM_A);
    cudaFuncSetAttribute(stageB_kernel, cudaFuncAttributeMaxDynamicSharedMemorySize, SMEM_B);

    ctx_kernel<<<64, HD>>>(ac, fWc);
    // v fastest in grid.x -> 16 variable-blocks of a token tile co-resident -> L2 reuse of embedding
    stageA_kernel<<<dim3(NV, NTOK / TM), 256, SMEM_A>>>(emb, sv_W1, sv_b1, sv_W2, sv_b2,
                                                        sv_Wg, sv_bg, sv_Wv, sv_bv, sv_ls, sv_lb);
    stageB_kernel<<<NTOK / TM, 256, SMEM_B>>>(fWsk, fbsk, fW1, fb1, fW2, fb2,
                                              fWg, fbg, fWv, fbv, fls, flb, out_sw, out_sg);
    stageC_kernel<<<NTOK / 16, 256>>>(out_sw, out_tc);
}

// round 3
// speedup vs baseline: 1.5089x; 1.5089x over previous
#include <cuda_runtime.h>
#include <cuda_bf16.h>
#include <math.h>
#include <stdint.h>

#define NTOK 32768        // B*T
#define HD   160          // hidden = embed
#define NV   16           // variables
#define TM   32           // token tile (stage B)
#define SPAD 33           // smem pad (stage B)
#define TA   64           // token tile (stage A mma)
#define PA   164          // stage A operand pitch (floats)  -> bank = 4g+t, conflict-free
#define PB   168          // stage A weight pitch (floats)   -> bank = 8t+g, conflict-free

static __device__ float g_tr[(size_t)NTOK * HD * NV];    // transformed [n][v][h]
static __device__ float g_embt[(size_t)NTOK * HD * NV];  // emb transposed [n][v][e]
static __device__ float g_ctx[64 * HD];                  // additional_context @ Wc

__device__ __forceinline__ float eluf(float x) { return x > 0.f ? x : expm1f(x); }
__device__ __forceinline__ float sigf(float x) { return 1.f / (1.f + expf(-x)); }
__device__ __forceinline__ float tf32r(float x) {
    float r; asm("cvt.rna.tf32.f32 %0, %1;" : "=f"(r) : "f"(x)); return r;
}

// m16n8k8 tf32 mma (sm_80+ legacy path; compiles at compute_103 base)
__device__ __forceinline__ void mma8(float* c, const float* a, float b0, float b1) {
    asm volatile(
        "mma.sync.aligned.m16n8k8.row.col.f32.tf32.tf32.f32 "
        "{%0,%1,%2,%3}, {%4,%5,%6,%7}, {%8,%9}, {%0,%1,%2,%3};"
        : "+f"(c[0]), "+f"(c[1]), "+f"(c[2]), "+f"(c[3])
        : "r"(__float_as_uint(a[0])), "r"(__float_as_uint(a[1])),
          "r"(__float_as_uint(a[2])), "r"(__float_as_uint(a[3])),
          "r"(__float_as_uint(b0)), "r"(__float_as_uint(b1)));
}

extern __shared__ float smem[];

// ---- stage A helpers ----
__device__ __forceinline__ void ldg_chunk(const float* __restrict__ W, int c,
                                          float4* wv, int tid) {
#pragma unroll
    for (int u = 0; u < 5; ++u) {
        int q = u * 256 + tid;
        int row = q / 40, c4 = q - row * 40;
        wv[u] = *(const float4*)(W + (size_t)(c * 32 + row) * HD + c4 * 4);
    }
}
__device__ __forceinline__ void sts_chunk(const float4* wv, float* s_Bh, float* s_Bl, int tid) {
#pragma unroll
    for (int u = 0; u < 5; ++u) {
        int q = u * 256 + tid;
        int row = q / 40, c4 = q - row * 40;
        float4 w = wv[u];
        float4 h, l;
        h.x = tf32r(w.x); l.x = tf32r(w.x - h.x);
        h.y = tf32r(w.y); l.y = tf32r(w.y - h.y);
        h.z = tf32r(w.z); l.z = tf32r(w.z - h.z);
        h.w = tf32r(w.w); l.w = tf32r(w.w - h.w);
        *(float4*)(s_Bh + row * PB + c4 * 4) = h;
        *(float4*)(s_Bl + row * PB + c4 * 4) = l;
    }
}

// 64x160 @ 160x160 in 3xTF32; acc[f][mf][r]
__device__ __forceinline__ void gemm_mma(const float* __restrict__ W,
    float acc[5][2][4], const float* s_Ah, const float* s_Al,
    float* s_Bh, float* s_Bl, int tid, int g, int t, int m0w, int n0w)
{
    float4 wv[5];
    ldg_chunk(W, 0, wv, tid);
    sts_chunk(wv, s_Bh, s_Bl, tid);
    __syncthreads();
#pragma unroll 1
    for (int c = 0; c < 5; ++c) {
        float4 wn[5];
        if (c < 4) ldg_chunk(W, c + 1, wn, tid);
#pragma unroll
        for (int s = 0; s < 4; ++s) {
            const int kk = c * 32 + s * 8;     // A k index (A fully resident)
            const int kb = s * 8;              // B k index (buffer)
            float ah[2][4], al[2][4];
#pragma unroll
            for (int mf = 0; mf < 2; ++mf) {
                int r0 = m0w + mf * 16 + g;
                ah[mf][0] = s_Ah[r0 * PA + kk + t];
                ah[mf][1] = s_Ah[(r0 + 8) * PA + kk + t];
                ah[mf][2] = s_Ah[r0 * PA + kk + t + 4];
                ah[mf][3] = s_Ah[(r0 + 8) * PA + kk + t + 4];
                al[mf][0] = s_Al[r0 * PA + kk + t];
                al[mf][1] = s_Al[(r0 + 8) * PA + kk + t];
                al[mf][2] = s_Al[r0 * PA + kk + t + 4];
                al[mf][3] = s_Al[(r0 + 8) * PA + kk + t + 4];
            }
#pragma unroll
            for (int f = 0; f < 5; ++f) {
                int nn = n0w + f * 8 + g;
                float bh0 = s_Bh[(kb + t) * PB + nn];
                float bh1 = s_Bh[(kb + t + 4) * PB + nn];
                float bl0 = s_Bl[(kb + t) * PB + nn];
                float bl1 = s_Bl[(kb + t + 4) * PB + nn];
#pragma unroll
                for (int mf = 0; mf < 2; ++mf) {
                    mma8(acc[f][mf], ah[mf], bh0, bh1);
                    mma8(acc[f][mf], ah[mf], bl0, bl1);
                    mma8(acc[f][mf], al[mf], bh0, bh1);
                }
            }
        }
        __syncthreads();
        if (c < 4) { sts_chunk(wn, s_Bh, s_Bl, tid); __syncthreads(); }
    }
}

#define ZERO_ACC(acc) \
    _Pragma("unroll") for (int f = 0; f < 5; ++f) \
    _Pragma("unroll") for (int mf = 0; mf < 2; ++mf) \
    _Pragma("unroll") for (int r = 0; r < 4; ++r) acc[f][mf][r] = 0.f;

__global__ void __launch_bounds__(256, 1) stageA_mma(
    const float* __restrict__ W1, const float* __restrict__ b1,
    const float* __restrict__ W2, const float* __restrict__ b2,
    const float* __restrict__ Wg, const float* __restrict__ bg,
    const float* __restrict__ Wv, const float* __restrict__ bv,
    const float* __restrict__ lns, const float* __restrict__ lnb)
{
    float* s_Ah  = smem;                   // [64][164]
    float* s_Al  = s_Ah + TA * PA;         // [64][164]
    float* s_x   = s_Al + TA * PA;         // [64][164] fp32 skip (becomes y)
    float* s_Bh  = s_x  + TA * PA;         // [32][168]
    float* s_Bl  = s_Bh + 32 * PB;         // [32][168]
    float* s_bias= s_Bl + 32 * PB;         // 6*160
    float* s_red = s_bias + 6 * HD;        // [64][2] mean/rstd

    const int v   = blockIdx.x;
    const int n0  = blockIdx.y * TA;
    const int tid = threadIdx.x;
    const int lane = tid & 31;
    const int wid  = tid >> 5;
    const int g = lane >> 2, t = lane & 3;
    const int m0w = (wid & 1) * 32;
    const int n0w = (wid >> 1) * 40;

    // biases / LN params
    for (int l = tid; l < HD; l += 256) {
        s_bias[l]          = b1[v * HD + l];
        s_bias[HD + l]     = b2[v * HD + l];
        s_bias[2*HD + l]   = bg[v * HD + l];
        s_bias[3*HD + l]   = bv[v * HD + l];
        s_bias[4*HD + l]   = lns[v * HD + l];
        s_bias[5*HD + l]   = lnb[v * HD + l];
    }

    // x tile: coalesced from g_embt; keep fp32 + split hi/lo
#pragma unroll
    for (int u = 0; u < 40; ++u) {
        int l = u * 256 + tid;
        int m = l / HD, j = l - m * HD;
        float x = g_embt[(size_t)(n0 + m) * (HD * NV) + (size_t)v * HD + j];
        s_x[m * PA + j] = x;
        float h = tf32r(x);
        s_Ah[m * PA + j] = h;
        s_Al[m * PA + j] = tf32r(x - h);
    }
    __syncthreads();

    float acc[5][2][4];

    // ---- GEMM1: h1 = elu(x@W1 + b1) ----
    ZERO_ACC(acc);
    gemm_mma(W1 + (size_t)v * HD * HD, acc, s_Ah, s_Al, s_Bh, s_Bl, tid, g, t, m0w, n0w);
#pragma unroll
    for (int f = 0; f < 5; ++f)
#pragma unroll
        for (int mf = 0; mf < 2; ++mf)
#pragma unroll
            for (int r = 0; r < 4; ++r) {
                int row = m0w + mf * 16 + g + (r >> 1) * 8;
                int col = n0w + f * 8 + 2 * t + (r & 1);
                float val = eluf(acc[f][mf][r] + s_bias[col]);
                float h = tf32r(val);
                s_Ah[row * PA + col] = h;
                s_Al[row * PA + col] = tf32r(val - h);
            }
    __syncthreads();

    // ---- GEMM2: h2 = h1@W2 + b2 ----
    ZERO_ACC(acc);
    gemm_mma(W2 + (size_t)v * HD * HD, acc, s_Ah, s_Al, s_Bh, s_Bl, tid, g, t, m0w, n0w);
    __syncthreads();   // all reads of h1 done before overwrite
#pragma unroll
    for (int f = 0; f < 5; ++f)
#pragma unroll
        for (int mf = 0; mf < 2; ++mf)
#pragma unroll
            for (int r = 0; r < 4; ++r) {
                int row = m0w + mf * 16 + g + (r >> 1) * 8;
                int col = n0w + f * 8 + 2 * t + (r & 1);
                float val = acc[f][mf][r] + s_bias[HD + col];
                float h = tf32r(val);
                s_Ah[row * PA + col] = h;
                s_Al[row * PA + col] = tf32r(val - h);
            }
    __syncthreads();

    // ---- GEMM3: gate = sigmoid(h2@Wg + bg) (kept in regs) ----
    ZERO_ACC(acc);
    gemm_mma(Wg + (size_t)v * HD * HD, acc, s_Ah, s_Al, s_Bh, s_Bl, tid, g, t, m0w, n0w);
    float gate[5][2][4];
#pragma unroll
    for (int f = 0; f < 5; ++f)
#pragma unroll
        for (int mf = 0; mf < 2; ++mf)
#pragma unroll
            for (int r = 0; r < 4; ++r) {
                int col = n0w + f * 8 + 2 * t + (r & 1);
                gate[f][mf][r] = sigf(acc[f][mf][r] + s_bias[2*HD + col]);
            }

    // ---- GEMM4: y = x + gate*(h2@Wv + bv) ----
    ZERO_ACC(acc);
    gemm_mma(Wv + (size_t)v * HD * HD, acc, s_Ah, s_Al, s_Bh, s_Bl, tid, g, t, m0w, n0w);
#pragma unroll
    for (int f = 0; f < 5; ++f)
#pragma unroll
        for (int mf = 0; mf < 2; ++mf)
#pragma unroll
            for (int r = 0; r < 4; ++r) {
                int row = m0w + mf * 16 + g + (r >> 1) * 8;
                int col = n0w + f * 8 + 2 * t + (r & 1);
                float val = acc[f][mf][r] + s_bias[3*HD + col];
                s_x[row * PA + col] = s_x[row * PA + col] + gate[f][mf][r] * val;
            }
    __syncthreads();

    // ---- LayerNorm over H=160, warp w handles rows 8w..8w+7 ----
#pragma unroll
    for (int rr = 0; rr < 8; ++rr) {
        int row = 8 * wid + rr;
        float s = 0.f, q = 0.f;
#pragma unroll
        for (int u = 0; u < 5; ++u) {
            float y = s_x[row * PA + u * 32 + lane];
            s += y; q += y * y;
        }
#pragma unroll
        for (int off = 16; off; off >>= 1) {
            s += __shfl_xor_sync(0xffffffffu, s, off);
            q += __shfl_xor_sync(0xffffffffu, q, off);
        }
        if (lane == 0) {
            float mean = s * (1.f / HD);
            float var  = q * (1.f / HD) - mean * mean;
            s_red[row * 2]     = mean;
            s_red[row * 2 + 1] = rsqrtf(var + 1e-5f);
        }
    }
    __syncthreads();

    // coalesced store to g_tr [n][v][h]
#pragma unroll
    for (int u = 0; u < 40; ++u) {
        int l = u * 256 + tid;
        int m = l / HD, j = l - m * HD;
        float mean = s_red[m * 2], rstd = s_red[m * 2 + 1];
        float yv = (s_x[m * PA + j] - mean) * rstd * s_bias[4*HD + j] + s_bias[5*HD + j];
        g_tr[(size_t)(n0 + m) * (HD * NV) + (size_t)v * HD + j] = yv;
    }
}

// ===================== transpose: emb[n][e][v] -> g_embt[n][v][e] =====================
__global__ void __launch_bounds__(256) transpose_kernel(const float* __restrict__ emb) {
    __shared__ float s[HD * 17];
    size_t n = blockIdx.x;
    int tid = threadIdx.x;
    const float* src = emb + n * (HD * NV);
    for (int l = tid; l < HD * NV; l += 256) {
        int e = l >> 4, vv = l & 15;
        s[e * 17 + vv] = src[l];
    }
    __syncthreads();
    float* dst = g_embt + n * (HD * NV);
    for (int l = tid; l < HD * NV; l += 256) {
        int vv = l / HD, e = l - vv * HD;
        dst[l] = s[e * 17 + vv];
    }
}

// ===================== stage B (fp32 CUDA-core, known good) =====================
__device__ __forceinline__ void load_wtile(float* sW, const float* __restrict__ W,
                                           int kt, int tid) {
#pragma unroll
    for (int t = 0; t < 20; ++t) {
        int l = tid + t * 256;
        int j = l % HD, kk = l / HD;
        sW[kk * HD + j] = W[(size_t)(kt * 32 + kk) * HD + j];
    }
}

__device__ __forceinline__ void gemm160(const float* sK, const float* __restrict__ W,
                                        float* sW, float acc[4][5], int r, int c, int tid) {
    for (int kt = 0; kt < 5; ++kt) {
        load_wtile(sW, W, kt, tid);
        __syncthreads();
#pragma unroll
        for (int kk = 0; kk < 32; ++kk) {
            const float* xk = sK + (kt * 32 + kk) * SPAD + r;
            float a0 = xk[0], a1 = xk[8], a2 = xk[16], a3 = xk[24];
            const float* wk = sW + kk * HD + c;
#pragma unroll
            for (int ji = 0; ji < 5; ++ji) {
                float w = wk[32 * ji];
                acc[0][ji] = fmaf(a0, w, acc[0][ji]);
                acc[1][ji] = fmaf(a1, w, acc[1][ji]);
                acc[2][ji] = fmaf(a2, w, acc[2][ji]);
                acc[3][ji] = fmaf(a3, w, acc[3][ji]);
            }
        }
        __syncthreads();
    }
}

__global__ void ctx_kernel(const float* __restrict__ ac, const float* __restrict__ Wc) {
    int b = blockIdx.x, j = threadIdx.x;
    float s = 0.f;
    for (int k = 0; k < HD; ++k)
        s = fmaf(ac[b * HD + k], Wc[k * HD + j], s);
    g_ctx[b * HD + j] = s;
}

__global__ void __launch_bounds__(256, 2) stageB_kernel(
    const float* __restrict__ Wskip, const float* __restrict__ bskip,
    const float* __restrict__ W1,    const float* __restrict__ b1,
    const float* __restrict__ W2,    const float* __restrict__ b2,
    const float* __restrict__ Wg,    const float* __restrict__ bg,
    const float* __restrict__ Wv,    const float* __restrict__ bv,
    const float* __restrict__ lns,   const float* __restrict__ lnb,
    float* __restrict__ out_sw, float* __restrict__ out_sg)
{
    float* s_h2 = smem;
    float* s_h3 = s_h2 + HD * SPAD;
    float* s_w  = s_h3 + HD * SPAD;
    float* s_f  = s_w  + 32 * HD;
    float* s_sk = s_f  + 32 * SPAD;
    float* s_gv = s_sk + 32 * 16;

    const int n0  = blockIdx.x * TM;
    const int tid = threadIdx.x;
    const int r   = tid >> 5;
    const int c   = tid & 31;
    const int bidx = n0 >> 9;

    float acc[4][5];
    float asx[4] = {0.f, 0.f, 0.f, 0.f};
#pragma unroll
    for (int i = 0; i < 4; ++i)
#pragma unroll
        for (int j = 0; j < 5; ++j) acc[i][j] = 0.f;

    for (int kt = 0; kt < 80; ++kt) {
        int k0 = kt * 32;
#pragma unroll
        for (int t = 0; t < 4; ++t) {
            int l = tid + t * 256;
            int kk = l & 31, m = l >> 5;
            s_f[kk * SPAD + m] = g_tr[(size_t)(n0 + m) * (HD * NV) + k0 + kk];
        }
#pragma unroll
        for (int t = 0; t < 20; ++t) {
            int l = tid + t * 256;
            int j = l % HD, kk = l / HD;
            int k = k0 + kk;
            int pk = (k % HD) * NV + (k / HD);
            s_w[kk * HD + j] = W1[(size_t)pk * HD + j];
        }
#pragma unroll
        for (int t = 0; t < 2; ++t) {
            int l = tid + t * 256;
            int kk = l >> 4, vv = l & 15;
            int k = k0 + kk;
            int pk = (k % HD) * NV + (k / HD);
            s_sk[kk * NV + vv] = Wskip[(size_t)pk * NV + vv];
        }
        __syncthreads();
#pragma unroll
        for (int kk = 0; kk < 32; ++kk) {
            const float* fk = s_f + kk * SPAD + r;
            float a0 = fk[0], a1 = fk[8], a2 = fk[16], a3 = fk[24];
            const float* wk = s_w + kk * HD + c;
#pragma unroll
            for (int ji = 0; ji < 5; ++ji) {
                float w = wk[32 * ji];
                acc[0][ji] = fmaf(a0, w, acc[0][ji]);
                acc[1][ji] = fmaf(a1, w, acc[1][ji]);
                acc[2][ji] = fmaf(a2, w, acc[2][ji]);
                acc[3][ji] = fmaf(a3, w, acc[3][ji]);
            }
            if (c < NV) {
                float ws = s_sk[kk * NV + c];
                asx[0] = fmaf(a0, ws, asx[0]);
                asx[1] = fmaf(a1, ws, asx[1]);
                asx[2] = fmaf(a2, ws, asx[2]);
                asx[3] = fmaf(a3, ws, asx[3]);
            }
        }
        __syncthreads();
    }

#pragma unroll
    for (int mi = 0; mi < 4; ++mi)
#pragma unroll
        for (int ji = 0; ji < 5; ++ji) {
            int j = c + 32 * ji;
            s_h2[j * SPAD + r + 8 * mi] = eluf(acc[mi][ji] + b1[j] + g_ctx[bidx * HD + j]);
        }
    __syncthreads();

#pragma unroll
    for (int i = 0; i < 4; ++i)
#pragma unroll
        for (int j = 0; j < 5; ++j) acc[i][j] = 0.f;
    gemm160(s_h2, W2, s_w, acc, r, c, tid);
#pragma unroll
    for (int mi = 0; mi < 4; ++mi)
#pragma unroll
        for (int ji = 0; ji < 5; ++ji) {
            int j = c + 32 * ji;
            s_h3[j * SPAD + r + 8 * mi] = acc[mi][ji] + b2[j];
        }
#pragma unroll
    for (int t = 0; t < 20; ++t) {
        int l = tid + t * 256;
        int cc = l & 31, k = l >> 5;
        s_gv[k * 32 + cc] = (cc < NV) ? Wg[k * NV + cc] : Wv[k * NV + (cc - NV)];
    }
    __syncthreads();

    float gv[4] = {0.f, 0.f, 0.f, 0.f};
#pragma unroll 8
    for (int k = 0; k < HD; ++k) {
        float w = s_gv[k * 32 + c];
        gv[0] = fmaf(s_h3[k * SPAD + r],      w, gv[0]);
        gv[1] = fmaf(s_h3[k * SPAD + r + 8],  w, gv[1]);
        gv[2] = fmaf(s_h3[k * SPAD + r + 16], w, gv[2]);
        gv[3] = fmaf(s_h3[k * SPAD + r + 24], w, gv[3]);
    }

    int vc = c & 15;
    float bgv = (c < NV) ? bg[vc] : bv[vc];
    float skb = bskip[vc];
    float lsc = lns[vc], lbc = lnb[vc];
#pragma unroll
    for (int mi = 0; mi < 4; ++mi) {
        float z = gv[mi] + bgv;
        float gval = (c < NV) ? sigf(z) : z;
        float partner = __shfl_xor_sync(0xffffffffu, gval, 16);
        float y = asx[mi] + skb + gval * partner;
        float s = y, q = y * y;
#pragma unroll
        for (int off = 8; off; off >>= 1) {
            s += __shfl_xor_sync(0xffffffffu, s, off);
            q += __shfl_xor_sync(0xffffffffu, q, off);
        }
        float mean = s * (1.f / 16.f);
        float var  = q * (1.f / 16.f) - mean * mean;
        float rstd = rsqrtf(var + 1e-5f);
        float logit = (y - mean) * rstd * lsc + lbc;
        float mx = logit;
#pragma unroll
        for (int off = 8; off; off >>= 1)
            mx = fmaxf(mx, __shfl_xor_sync(0xffffffffu, mx, off));
        float e = expf(logit - mx);
        float se = e;
#pragma unroll
        for (int off = 8; off; off >>= 1)
            se += __shfl_xor_sync(0xffffffffu, se, off);
        if (c < NV) {
            int n = n0 + r + 8 * mi;
            out_sw[(size_t)n * NV + c] = e / se;
            out_sg[(size_t)n * NV + c] = gval;
        }
    }
}

__global__ void __launch_bounds__(256) stageC_kernel(const float* __restrict__ sw,
                                                     float* __restrict__ out_tc) {
    __shared__ float s_w[16 * NV];
    int n0 = blockIdx.x * 16;
    int tid = threadIdx.x;
    s_w[tid] = sw[(size_t)n0 * NV + tid];
    __syncthreads();
#pragma unroll
    for (int t = 0; t < 10; ++t) {
        int l = tid + t * 256;
        int h = l % HD, m = l / HD;
        const float* row = g_tr + (size_t)(n0 + m) * (HD * NV) + h;
        float s = 0.f;
#pragma unroll
        for (int vv = 0; vv < NV; ++vv)
            s = fmaf(row[vv * HD], s_w[m * NV + vv], s);
        out_tc[(size_t)(n0 + m) * HD + h] = s;
    }
}

// ===================== launch =====================
extern "C" void kernel_launch(void* const* d_in, const int* in_sizes, int n_in,
                              void* d_out, int out_size)
{
    const float* emb   = (const float*)d_in[0];
    const float* ac    = (const float*)d_in[1];
    const float* sv_W1 = (const float*)d_in[2];
    const float* sv_b1 = (const float*)d_in[3];
    const float* sv_W2 = (const float*)d_in[4];
    const float* sv_b2 = (const float*)d_in[5];
    const float* sv_Wg = (const float*)d_in[6];
    const float* sv_bg = (const float*)d_in[7];
    const float* sv_Wv = (const float*)d_in[8];
    const float* sv_bv = (const float*)d_in[9];
    const float* sv_ls = (const float*)d_in[10];
    const float* sv_lb = (const float*)d_in[11];
    const float* fWsk  = (const float*)d_in[12];
    const float* fbsk  = (const float*)d_in[13];
    const float* fW1   = (const float*)d_in[14];
    const float* fb1   = (const float*)d_in[15];
    const float* fWc   = (const float*)d_in[16];
    const float* fW2   = (const float*)d_in[17];
    const float* fb2   = (const float*)d_in[18];
    const float* fWg   = (const float*)d_in[19];
    const float* fbg   = (const float*)d_in[20];
    const float* fWv   = (const float*)d_in[21];
    const float* fbv   = (const float*)d_in[22];
    const float* fls   = (const float*)d_in[23];
    const float* flb   = (const float*)d_in[24];

    float* out    = (float*)d_out;
    float* out_tc = out;
    float* out_sw = out + (size_t)NTOK * HD;
    float* out_sg = out_sw + (size_t)NTOK * NV;

    const int SMEM_A = (3 * TA * PA + 2 * 32 * PB + 6 * HD + 128) * (int)sizeof(float); // ~173.8KB
    const int SMEM_B = (2 * HD * SPAD + 32 * HD + 32 * SPAD + 32 * 16 + HD * 32) * (int)sizeof(float);
    cudaFuncSetAttribute(stageA_mma, cudaFuncAttributeMaxDynamicSharedMemorySize, SMEM_A);
    cudaFuncSetAttribute(stageB_kernel, cudaFuncAttributeMaxDynamicSharedMemorySize, SMEM_B);

    ctx_kernel<<<64, HD>>>(ac, fWc);
    transpose_kernel<<<NTOK, 256>>>(emb);
    // v fastest -> weight working set (6.5MB) stays L2-resident across the wave
    stageA_mma<<<dim3(NV, NTOK / TA), 256, SMEM_A>>>(sv_W1, sv_b1, sv_W2, sv_b2,
                                                     sv_Wg, sv_bg, sv_Wv, sv_bv, sv_ls, sv_lb);
    stageB_kernel<<<NTOK / TM, 256, SMEM_B>>>(fWsk, fbsk, fW1, fb1, fW2, fb2,
                                              fWg, fbg, fWv, fbv, fls, flb, out_sw, out_sg);
    stageC_kernel<<<NTOK / 16, 256>>>(out_sw, out_tc);
}

// round 4
// speedup vs baseline: 2.0219x; 1.3400x over previous
#include <cuda_runtime.h>
#include <cuda_bf16.h>
#include <math.h>
#include <stdint.h>

#define NTOK 32768        // B*T
#define HD   160          // hidden = embed
#define NV   16           // variables
#define TM   32           // token tile (stage B)
#define SPAD 33           // smem pad (stage B)
#define TA   64           // token tile (stage A)
#define PA2  84           // packed-A pitch (u32)  -> bank 20g+t, conflict-free
#define PB2  168          // packed-B pitch (u32)  -> bank 8t+g,  conflict-free
#define PAX  164          // fp32 skip pitch
#define CHUNK_U32 (2*16*PB2)   // 5376 u32: hi tile [16][168] then lo tile

static __device__ float g_tr[(size_t)NTOK * HD * NV];    // transformed [n][v][h]
static __device__ float g_embt[(size_t)NTOK * HD * NV];  // emb transposed [n][v][e]
static __device__ float g_ctx[64 * HD];                  // additional_context @ Wc
static __device__ __align__(16) uint32_t g_wsplA[(size_t)16 * 4 * 5 * CHUNK_U32]; // split weights

__device__ __forceinline__ float eluf(float x) { return x > 0.f ? x : expm1f(x); }
__device__ __forceinline__ float sigf(float x) { return 1.f / (1.f + expf(-x)); }

__device__ __forceinline__ uint32_t smem_u32(const void* p) {
    uint32_t a;
    asm("{ .reg .u64 t; cvta.to.shared.u64 t, %1; cvt.u32.u64 %0, t; }" : "=r"(a) : "l"(p));
    return a;
}
__device__ __forceinline__ void cp16(uint32_t saddr, const uint32_t* g) {
    asm volatile("cp.async.cg.shared.global [%0], [%1], 16;" :: "r"(saddr), "l"(g));
}
#define CP_COMMIT() asm volatile("cp.async.commit_group;" ::: "memory")
#define CP_WAIT1()  asm volatile("cp.async.wait_group 1;" ::: "memory")
#define CP_WAIT0()  asm volatile("cp.async.wait_group 0;" ::: "memory")

__device__ __forceinline__ void mma16(float* c, const uint32_t* a, const uint32_t* b) {
    asm volatile("mma.sync.aligned.m16n8k16.row.col.f32.bf16.bf16.f32 "
        "{%0,%1,%2,%3}, {%4,%5,%6,%7}, {%8,%9}, {%0,%1,%2,%3};"
        : "+f"(c[0]), "+f"(c[1]), "+f"(c[2]), "+f"(c[3])
        : "r"(a[0]), "r"(a[1]), "r"(a[2]), "r"(a[3]), "r"(b[0]), "r"(b[1]));
}

__device__ __forceinline__ void splitpack(float v0, float v1, uint32_t& hi, uint32_t& lo) {
    __nv_bfloat16 h0 = __float2bfloat16(v0), h1 = __float2bfloat16(v1);
    __nv_bfloat16 l0 = __float2bfloat16(v0 - __bfloat162float(h0));
    __nv_bfloat16 l1 = __float2bfloat16(v1 - __bfloat162float(h1));
    __nv_bfloat162 hh; hh.x = h0; hh.y = h1;
    __nv_bfloat162 ll; ll.x = l0; ll.y = l1;
    hi = *reinterpret_cast<uint32_t*>(&hh);
    lo = *reinterpret_cast<uint32_t*>(&ll);
}

// ===================== prep: split & pack per-variable weights =====================
__global__ void __launch_bounds__(256) prepA_kernel(
    const float* __restrict__ W1, const float* __restrict__ W2,
    const float* __restrict__ Wg, const float* __restrict__ Wv)
{
    int b = blockIdx.x;                 // v*20 + mat*5 + c
    int c = b % 5, mat = (b / 5) & 3, v = b / 20;
    const float* W = (mat == 0 ? W1 : mat == 1 ? W2 : mat == 2 ? Wg : Wv) + (size_t)v * HD * HD;
    uint32_t* dst = g_wsplA + (size_t)b * CHUNK_U32;
    for (int i = threadIdx.x; i < 16 * PB2; i += 256) {
        int pr = i / PB2, col = i - pr * PB2;
        float w0 = 0.f, w1 = 0.f;
        if (col < HD) {
            int k0 = c * 32 + 2 * pr;
            w0 = W[(size_t)k0 * HD + col];
            w1 = W[(size_t)(k0 + 1) * HD + col];
        }
        uint32_t hi, lo;
        splitpack(w0, w1, hi, lo);
        dst[i] = hi;
        dst[16 * PB2 + i] = lo;
    }
}

// ===================== stage A (bf16 split-3 mma, cp.async pipelined) =====================
extern __shared__ float smem[];

__device__ __forceinline__ void stage_chunk(uint32_t* sdst, const uint32_t* __restrict__ g, int tid) {
    uint32_t s = smem_u32(sdst);
#pragma unroll
    for (int i = 0; i < 5; ++i) {
        int q = i * 256 + tid;
        cp16(s + q * 16, g + q * 4);
    }
    int q = 1280 + tid;
    if (q < 1344) cp16(s + q * 16, g + q * 4);
}

__device__ __forceinline__ void loadB(const uint32_t* Bh, const uint32_t* Bl, int s,
                                      uint32_t bh[5][2], uint32_t bl[5][2],
                                      int g, int t, int n0w) {
#pragma unroll
    for (int f = 0; f < 5; ++f) {
        int nn = n0w + f * 8 + g;
        bh[f][0] = Bh[(s * 8 + t) * PB2 + nn];
        bh[f][1] = Bh[(s * 8 + 4 + t) * PB2 + nn];
        bl[f][0] = Bl[(s * 8 + t) * PB2 + nn];
        bl[f][1] = Bl[(s * 8 + 4 + t) * PB2 + nn];
    }
}

__device__ __forceinline__ void loadA(const uint32_t* s_Ah2, const uint32_t* s_Al2, int kp,
                                      uint32_t ah[2][4], uint32_t al[2][4],
                                      int g, int t, int m0w) {
#pragma unroll
    for (int mf = 0; mf < 2; ++mf) {
        int r0 = (m0w + mf * 16 + g) * PA2;
        int r1 = r0 + 8 * PA2;
        ah[mf][0] = s_Ah2[r0 + kp + t];     ah[mf][1] = s_Ah2[r1 + kp + t];
        ah[mf][2] = s_Ah2[r0 + kp + 4 + t]; ah[mf][3] = s_Ah2[r1 + kp + 4 + t];
        al[mf][0] = s_Al2[r0 + kp + t];     al[mf][1] = s_Al2[r1 + kp + t];
        al[mf][2] = s_Al2[r0 + kp + 4 + t]; al[mf][3] = s_Al2[r1 + kp + 4 + t];
    }
}

__device__ __forceinline__ void mma_chunk(const uint32_t* sB, float acc[5][2][4],
                                          const uint32_t* s_Ah2, const uint32_t* s_Al2,
                                          int kp0, int g, int t, int m0w, int n0w) {
    const uint32_t* Bh = sB;
    const uint32_t* Bl = sB + 16 * PB2;
    uint32_t bh0[5][2], bl0[5][2], bh1[5][2], bl1[5][2];
    loadB(Bh, Bl, 0, bh0, bl0, g, t, n0w);

    uint32_t ah[2][4], al[2][4];
    loadA(s_Ah2, s_Al2, kp0, ah, al, g, t, m0w);
    loadB(Bh, Bl, 1, bh1, bl1, g, t, n0w);      // prefetch step 1
#pragma unroll
    for (int f = 0; f < 5; ++f)
#pragma unroll
        for (int mf = 0; mf < 2; ++mf) {
            mma16(acc[f][mf], ah[mf], bh0[f]);
            mma16(acc[f][mf], ah[mf], bl0[f]);
            mma16(acc[f][mf], al[mf], bh0[f]);
        }
    loadA(s_Ah2, s_Al2, kp0 + 8, ah, al, g, t, m0w);
#pragma unroll
    for (int f = 0; f < 5; ++f)
#pragma unroll
        for (int mf = 0; mf < 2; ++mf) {
            mma16(acc[f][mf], ah[mf], bh1[f]);
            mma16(acc[f][mf], ah[mf], bl1[f]);
            mma16(acc[f][mf], al[mf], bh1[f]);
        }
}

__device__ __forceinline__ void gemm_bf16(const uint32_t* __restrict__ gW,
                                          const uint32_t* __restrict__ gWnext,
                                          uint32_t* sB0, uint32_t* sB1,
                                          float acc[5][2][4],
                                          const uint32_t* s_Ah2, const uint32_t* s_Al2,
                                          int par0, int tid, int g, int t, int m0w, int n0w) {
#pragma unroll 1
    for (int c = 0; c < 5; ++c) {
        uint32_t* cur = ((par0 + c) & 1) ? sB1 : sB0;
        uint32_t* nxt = ((par0 + c) & 1) ? sB0 : sB1;
        if (c < 4) {
            stage_chunk(nxt, gW + (size_t)(c + 1) * CHUNK_U32, tid);
            CP_COMMIT(); CP_WAIT1();
        } else if (gWnext) {
            stage_chunk(nxt, gWnext, tid);
            CP_COMMIT(); CP_WAIT1();
        } else {
            CP_WAIT0();
        }
        __syncthreads();
        mma_chunk(cur, acc, s_Ah2, s_Al2, c * 16, g, t, m0w, n0w);
        __syncthreads();
    }
}

#define ZERO_ACC(acc) \
    _Pragma("unroll") for (int f = 0; f < 5; ++f) \
    _Pragma("unroll") for (int mf = 0; mf < 2; ++mf) \
    _Pragma("unroll") for (int r = 0; r < 4; ++r) acc[f][mf][r] = 0.f;

__global__ void __launch_bounds__(256, 1) stageA_mma(
    const float* __restrict__ b1, const float* __restrict__ b2,
    const float* __restrict__ bg, const float* __restrict__ bv,
    const float* __restrict__ lns, const float* __restrict__ lnb)
{
    float* s_x    = smem;                      // [64][164] fp32 skip -> y
    float* s_bias = s_x + TA * PAX;            // 6*160
    float* s_red  = s_bias + 6 * HD;           // [64][2]
    uint32_t* s_Ah2 = (uint32_t*)(s_red + 128);      // [64][84] packed hi
    uint32_t* s_Al2 = s_Ah2 + TA * PA2;              // [64][84] packed lo
    uint32_t* sB0   = s_Al2 + TA * PA2;              // 5376 u32
    uint32_t* sB1   = sB0 + CHUNK_U32;               // 5376 u32

    const int v   = blockIdx.x;
    const int n0  = blockIdx.y * TA;
    const int tid = threadIdx.x;
    const int lane = tid & 31;
    const int wid  = tid >> 5;
    const int g = lane >> 2, t = lane & 3;
    const int m0w = (wid & 1) * 32;
    const int n0w = (wid >> 1) * 40;
    const int pib = n0w / 2;                   // pair-index base for this warp

    const uint32_t* wbase = g_wsplA + (size_t)v * 20 * CHUNK_U32;

    // prestage chunk (mat0, c0) ASAP — overlaps x-tile load
    stage_chunk(sB0, wbase, tid);
    CP_COMMIT();

    for (int l = tid; l < HD; l += 256) {
        s_bias[l]          = b1[v * HD + l];
        s_bias[HD + l]     = b2[v * HD + l];
        s_bias[2*HD + l]   = bg[v * HD + l];
        s_bias[3*HD + l]   = bv[v * HD + l];
        s_bias[4*HD + l]   = lns[v * HD + l];
        s_bias[5*HD + l]   = lnb[v * HD + l];
    }

    // x tile: fp32 into s_x, packed bf16 split into A
#pragma unroll
    for (int u = 0; u < 20; ++u) {
        int p = u * 256 + tid;                 // pair index, 64*80 total
        int row = p / 80, pc = p - row * 80;
        float2 xv = *(const float2*)(g_embt + (size_t)(n0 + row) * (HD * NV) + (size_t)v * HD + 2 * pc);
        s_x[row * PAX + 2 * pc]     = xv.x;
        s_x[row * PAX + 2 * pc + 1] = xv.y;
        uint32_t hi, lo;
        splitpack(xv.x, xv.y, hi, lo);
        s_Ah2[row * PA2 + pc] = hi;
        s_Al2[row * PA2 + pc] = lo;
    }
    __syncthreads();

    float acc[5][2][4];

    // ---- GEMM1: h1 = elu(x@W1 + b1) ----
    ZERO_ACC(acc);
    gemm_bf16(wbase, wbase + 5 * CHUNK_U32, sB0, sB1, acc, s_Ah2, s_Al2, 0, tid, g, t, m0w, n0w);
#pragma unroll
    for (int f = 0; f < 5; ++f) {
        int col0 = n0w + f * 8 + 2 * t;
        int pi = pib + f * 4 + t;
#pragma unroll
        for (int mf = 0; mf < 2; ++mf) {
            int r0 = m0w + mf * 16 + g;
            float v00 = eluf(acc[f][mf][0] + s_bias[col0]);
            float v01 = eluf(acc[f][mf][1] + s_bias[col0 + 1]);
            float v10 = eluf(acc[f][mf][2] + s_bias[col0]);
            float v11 = eluf(acc[f][mf][3] + s_bias[col0 + 1]);
            splitpack(v00, v01, s_Ah2[r0 * PA2 + pi], s_Al2[r0 * PA2 + pi]);
            splitpack(v10, v11, s_Ah2[(r0 + 8) * PA2 + pi], s_Al2[(r0 + 8) * PA2 + pi]);
        }
    }

    // ---- GEMM2: h2 = h1@W2 + b2 ----
    ZERO_ACC(acc);
    gemm_bf16(wbase + 5 * CHUNK_U32, wbase + 10 * CHUNK_U32, sB0, sB1, acc, s_Ah2, s_Al2, 1, tid, g, t, m0w, n0w);
#pragma unroll
    for (int f = 0; f < 5; ++f) {
        int col0 = n0w + f * 8 + 2 * t;
        int pi = pib + f * 4 + t;
#pragma unroll
        for (int mf = 0; mf < 2; ++mf) {
            int r0 = m0w + mf * 16 + g;
            float v00 = acc[f][mf][0] + s_bias[HD + col0];
            float v01 = acc[f][mf][1] + s_bias[HD + col0 + 1];
            float v10 = acc[f][mf][2] + s_bias[HD + col0];
            float v11 = acc[f][mf][3] + s_bias[HD + col0 + 1];
            splitpack(v00, v01, s_Ah2[r0 * PA2 + pi], s_Al2[r0 * PA2 + pi]);
            splitpack(v10, v11, s_Ah2[(r0 + 8) * PA2 + pi], s_Al2[(r0 + 8) * PA2 + pi]);
        }
    }

    // ---- GEMM3: gate = sigmoid(h2@Wg + bg), kept in regs ----
    ZERO_ACC(acc);
    gemm_bf16(wbase + 10 * CHUNK_U32, wbase + 15 * CHUNK_U32, sB0, sB1, acc, s_Ah2, s_Al2, 0, tid, g, t, m0w, n0w);
    float gate[5][2][4];
#pragma unroll
    for (int f = 0; f < 5; ++f)
#pragma unroll
        for (int mf = 0; mf < 2; ++mf)
#pragma unroll
            for (int r = 0; r < 4; ++r) {
                int col = n0w + f * 8 + 2 * t + (r & 1);
                gate[f][mf][r] = sigf(acc[f][mf][r] + s_bias[2*HD + col]);
            }

    // ---- GEMM4: y = x + gate*(h2@Wv + bv) ----
    ZERO_ACC(acc);
    gemm_bf16(wbase + 15 * CHUNK_U32, (const uint32_t*)0, sB0, sB1, acc, s_Ah2, s_Al2, 1, tid, g, t, m0w, n0w);
#pragma unroll
    for (int f = 0; f < 5; ++f)
#pragma unroll
        for (int mf = 0; mf < 2; ++mf)
#pragma unroll
            for (int r = 0; r < 4; ++r) {
                int row = m0w + mf * 16 + g + (r >> 1) * 8;
                int col = n0w + f * 8 + 2 * t + (r & 1);
                float val = acc[f][mf][r] + s_bias[3*HD + col];
                s_x[row * PAX + col] = s_x[row * PAX + col] + gate[f][mf][r] * val;
            }
    __syncthreads();

    // ---- LayerNorm over H=160: warp w owns rows 8w..8w+7 ----
#pragma unroll
    for (int rr = 0; rr < 8; ++rr) {
        int row = 8 * wid + rr;
        float s = 0.f, q = 0.f;
#pragma unroll
        for (int u = 0; u < 5; ++u) {
            float y = s_x[row * PAX + u * 32 + lane];
            s += y; q += y * y;
        }
#pragma unroll
        for (int off = 16; off; off >>= 1) {
            s += __shfl_xor_sync(0xffffffffu, s, off);
            q += __shfl_xor_sync(0xffffffffu, q, off);
        }
        if (lane == 0) {
            float mean = s * (1.f / HD);
            float var  = q * (1.f / HD) - mean * mean;
            s_red[row * 2]     = mean;
            s_red[row * 2 + 1] = rsqrtf(var + 1e-5f);
        }
    }
    __syncthreads();

#pragma unroll
    for (int u = 0; u < 40; ++u) {
        int l = u * 256 + tid;
        int m = l / HD, j = l - m * HD;
        float mean = s_red[m * 2], rstd = s_red[m * 2 + 1];
        float yv = (s_x[m * PAX + j] - mean) * rstd * s_bias[4*HD + j] + s_bias[5*HD + j];
        g_tr[(size_t)(n0 + m) * (HD * NV) + (size_t)v * HD + j] = yv;
    }
}

// ===================== transpose: emb[n][e][v] -> g_embt[n][v][e] =====================
__global__ void __launch_bounds__(256) transpose_kernel(const float* __restrict__ emb) {
    __shared__ float s[HD * 17];
    size_t n = blockIdx.x;
    int tid = threadIdx.x;
    const float* src = emb + n * (HD * NV);
    for (int l = tid; l < HD * NV; l += 256) {
        int e = l >> 4, vv = l & 15;
        s[e * 17 + vv] = src[l];
    }
    __syncthreads();
    float* dst = g_embt + n * (HD * NV);
    for (int l = tid; l < HD * NV; l += 256) {
        int vv = l / HD, e = l - vv * HD;
        dst[l] = s[e * 17 + vv];
    }
}

// ===================== stage B (fp32 CUDA-core, known good) =====================
__device__ __forceinline__ void load_wtile(float* sW, const float* __restrict__ W,
                                           int kt, int tid) {
#pragma unroll
    for (int t = 0; t < 20; ++t) {
        int l = tid + t * 256;
        int j = l % HD, kk = l / HD;
        sW[kk * HD + j] = W[(size_t)(kt * 32 + kk) * HD + j];
    }
}

__device__ __forceinline__ void gemm160(const float* sK, const float* __restrict__ W,
                                        float* sW, float acc[4][5], int r, int c, int tid) {
    for (int kt = 0; kt < 5; ++kt) {
        load_wtile(sW, W, kt, tid);
        __syncthreads();
#pragma unroll
        for (int kk = 0; kk < 32; ++kk) {
            const float* xk = sK + (kt * 32 + kk) * SPAD + r;
            float a0 = xk[0], a1 = xk[8], a2 = xk[16], a3 = xk[24];
            const float* wk = sW + kk * HD + c;
#pragma unroll
            for (int ji = 0; ji < 5; ++ji) {
                float w = wk[32 * ji];
                acc[0][ji] = fmaf(a0, w, acc[0][ji]);
                acc[1][ji] = fmaf(a1, w, acc[1][ji]);
                acc[2][ji] = fmaf(a2, w, acc[2][ji]);
                acc[3][ji] = fmaf(a3, w, acc[3][ji]);
            }
        }
        __syncthreads();
    }
}

__global__ void ctx_kernel(const float* __restrict__ ac, const float* __restrict__ Wc) {
    int b = blockIdx.x, j = threadIdx.x;
    float s = 0.f;
    for (int k = 0; k < HD; ++k)
        s = fmaf(ac[b * HD + k], Wc[k * HD + j], s);
    g_ctx[b * HD + j] = s;
}

__global__ void __launch_bounds__(256, 2) stageB_kernel(
    const float* __restrict__ Wskip, const float* __restrict__ bskip,
    const float* __restrict__ W1,    const float* __restrict__ b1,
    const float* __restrict__ W2,    const float* __restrict__ b2,
    const float* __restrict__ Wg,    const float* __restrict__ bg,
    const float* __restrict__ Wv,    const float* __restrict__ bv,
    const float* __restrict__ lns,   const float* __restrict__ lnb,
    float* __restrict__ out_sw, float* __restrict__ out_sg)
{
    float* s_h2 = smem;
    float* s_h3 = s_h2 + HD * SPAD;
    float* s_w  = s_h3 + HD * SPAD;
    float* s_f  = s_w  + 32 * HD;
    float* s_sk = s_f  + 32 * SPAD;
    float* s_gv = s_sk + 32 * 16;

    const int n0  = blockIdx.x * TM;
    const int tid = threadIdx.x;
    const int r   = tid >> 5;
    const int c   = tid & 31;
    const int bidx = n0 >> 9;

    float acc[4][5];
    float asx[4] = {0.f, 0.f, 0.f, 0.f};
#pragma unroll
    for (int i = 0; i < 4; ++i)
#pragma unroll
        for (int j = 0; j < 5; ++j) acc[i][j] = 0.f;

    for (int kt = 0; kt < 80; ++kt) {
        int k0 = kt * 32;
#pragma unroll
        for (int t = 0; t < 4; ++t) {
            int l = tid + t * 256;
            int kk = l & 31, m = l >> 5;
            s_f[kk * SPAD + m] = g_tr[(size_t)(n0 + m) * (HD * NV) + k0 + kk];
        }
#pragma unroll
        for (int t = 0; t < 20; ++t) {
            int l = tid + t * 256;
            int j = l % HD, kk = l / HD;
            int k = k0 + kk;
            int pk = (k % HD) * NV + (k / HD);
            s_w[kk * HD + j] = W1[(size_t)pk * HD + j];
        }
#pragma unroll
        for (int t = 0; t < 2; ++t) {
            int l = tid + t * 256;
            int kk = l >> 4, vv = l & 15;
            int k = k0 + kk;
            int pk = (k % HD) * NV + (k / HD);
            s_sk[kk * NV + vv] = Wskip[(size_t)pk * NV + vv];
        }
        __syncthreads();
#pragma unroll
        for (int kk = 0; kk < 32; ++kk) {
            const float* fk = s_f + kk * SPAD + r;
            float a0 = fk[0], a1 = fk[8], a2 = fk[16], a3 = fk[24];
            const float* wk = s_w + kk * HD + c;
#pragma unroll
            for (int ji = 0; ji < 5; ++ji) {
                float w = wk[32 * ji];
                acc[0][ji] = fmaf(a0, w, acc[0][ji]);
                acc[1][ji] = fmaf(a1, w, acc[1][ji]);
                acc[2][ji] = fmaf(a2, w, acc[2][ji]);
                acc[3][ji] = fmaf(a3, w, acc[3][ji]);
            }
            if (c < NV) {
                float ws = s_sk[kk * NV + c];
                asx[0] = fmaf(a0, ws, asx[0]);
                asx[1] = fmaf(a1, ws, asx[1]);
                asx[2] = fmaf(a2, ws, asx[2]);
                asx[3] = fmaf(a3, ws, asx[3]);
            }
        }
        __syncthreads();
    }

#pragma unroll
    for (int mi = 0; mi < 4; ++mi)
#pragma unroll
        for (int ji = 0; ji < 5; ++ji) {
            int j = c + 32 * ji;
            s_h2[j * SPAD + r + 8 * mi] = eluf(acc[mi][ji] + b1[j] + g_ctx[bidx * HD + j]);
        }
    __syncthreads();

#pragma unroll
    for (int i = 0; i < 4; ++i)
#pragma unroll
        for (int j = 0; j < 5; ++j) acc[i][j] = 0.f;
    gemm160(s_h2, W2, s_w, acc, r, c, tid);
#pragma unroll
    for (int mi = 0; mi < 4; ++mi)
#pragma unroll
        for (int ji = 0; ji < 5; ++ji) {
            int j = c + 32 * ji;
            s_h3[j * SPAD + r + 8 * mi] = acc[mi][ji] + b2[j];
        }
#pragma unroll
    for (int t = 0; t < 20; ++t) {
        int l = tid + t * 256;
        int cc = l & 31, k = l >> 5;
        s_gv[k * 32 + cc] = (cc < NV) ? Wg[k * NV + cc] : Wv[k * NV + (cc - NV)];
    }
    __syncthreads();

    float gv[4] = {0.f, 0.f, 0.f, 0.f};
#pragma unroll 8
    for (int k = 0; k < HD; ++k) {
        float w = s_gv[k * 32 + c];
        gv[0] = fmaf(s_h3[k * SPAD + r],      w, gv[0]);
        gv[1] = fmaf(s_h3[k * SPAD + r + 8],  w, gv[1]);
        gv[2] = fmaf(s_h3[k * SPAD + r + 16], w, gv[2]);
        gv[3] = fmaf(s_h3[k * SPAD + r + 24], w, gv[3]);
    }

    int vc = c & 15;
    float bgv = (c < NV) ? bg[vc] : bv[vc];
    float skb = bskip[vc];
    float lsc = lns[vc], lbc = lnb[vc];
#pragma unroll
    for (int mi = 0; mi < 4; ++mi) {
        float z = gv[mi] + bgv;
        float gval = (c < NV) ? sigf(z) : z;
        float partner = __shfl_xor_sync(0xffffffffu, gval, 16);
        float y = asx[mi] + skb + gval * partner;
        float s = y, q = y * y;
#pragma unroll
        for (int off = 8; off; off >>= 1) {
            s += __shfl_xor_sync(0xffffffffu, s, off);
            q += __shfl_xor_sync(0xffffffffu, q, off);
        }
        float mean = s * (1.f / 16.f);
        float var  = q * (1.f / 16.f) - mean * mean;
        float rstd = rsqrtf(var + 1e-5f);
        float logit = (y - mean) * rstd * lsc + lbc;
        float mx = logit;
#pragma unroll
        for (int off = 8; off; off >>= 1)
            mx = fmaxf(mx, __shfl_xor_sync(0xffffffffu, mx, off));
        float e = expf(logit - mx);
        float se = e;
#pragma unroll
        for (int off = 8; off; off >>= 1)
            se += __shfl_xor_sync(0xffffffffu, se, off);
        if (c < NV) {
            int n = n0 + r + 8 * mi;
            out_sw[(size_t)n * NV + c] = e / se;
            out_sg[(size_t)n * NV + c] = gval;
        }
    }
}

__global__ void __launch_bounds__(256) stageC_kernel(const float* __restrict__ sw,
                                                     float* __restrict__ out_tc) {
    __shared__ float s_w[16 * NV];
    int n0 = blockIdx.x * 16;
    int tid = threadIdx.x;
    s_w[tid] = sw[(size_t)n0 * NV + tid];
    __syncthreads();
#pragma unroll
    for (int t = 0; t < 10; ++t) {
        int l = tid + t * 256;
        int h = l % HD, m = l / HD;
        const float* row = g_tr + (size_t)(n0 + m) * (HD * NV) + h;
        float s = 0.f;
#pragma unroll
        for (int vv = 0; vv < NV; ++vv)
            s = fmaf(row[vv * HD], s_w[m * NV + vv], s);
        out_tc[(size_t)(n0 + m) * HD + h] = s;
    }
}

// ===================== launch =====================
extern "C" void kernel_launch(void* const* d_in, const int* in_sizes, int n_in,
                              void* d_out, int out_size)
{
    const float* emb   = (const float*)d_in[0];
    const float* ac    = (const float*)d_in[1];
    const float* sv_W1 = (const float*)d_in[2];
    const float* sv_b1 = (const float*)d_in[3];
    const float* sv_W2 = (const float*)d_in[4];
    const float* sv_b2 = (const float*)d_in[5];
    const float* sv_Wg = (const float*)d_in[6];
    const float* sv_bg = (const float*)d_in[7];
    const float* sv_Wv = (const float*)d_in[8];
    const float* sv_bv = (const float*)d_in[9];
    const float* sv_ls = (const float*)d_in[10];
    const float* sv_lb = (const float*)d_in[11];
    const float* fWsk  = (const float*)d_in[12];
    const float* fbsk  = (const float*)d_in[13];
    const float* fW1   = (const float*)d_in[14];
    const float* fb1   = (const float*)d_in[15];
    const float* fWc   = (const float*)d_in[16];
    const float* fW2   = (const float*)d_in[17];
    const float* fb2   = (const float*)d_in[18];
    const float* fWg   = (const float*)d_in[19];
    const float* fbg   = (const float*)d_in[20];
    const float* fWv   = (const float*)d_in[21];
    const float* fbv   = (const float*)d_in[22];
    const float* fls   = (const float*)d_in[23];
    const float* flb   = (const float*)d_in[24];

    float* out    = (float*)d_out;
    float* out_tc = out;
    float* out_sw = out + (size_t)NTOK * HD;
    float* out_sg = out_sw + (size_t)NTOK * NV;

    const int SMEM_A = (TA * PAX + 6 * HD + 128) * 4 + (2 * TA * PA2 + 2 * CHUNK_U32) * 4; // 132352
    const int SMEM_B = (2 * HD * SPAD + 32 * HD + 32 * SPAD + 32 * 16 + HD * 32) * (int)sizeof(float);
    cudaFuncSetAttribute(stageA_mma, cudaFuncAttributeMaxDynamicSharedMemorySize, SMEM_A);
    cudaFuncSetAttribute(stageB_kernel, cudaFuncAttributeMaxDynamicSharedMemorySize, SMEM_B);

    prepA_kernel<<<320, 256>>>(sv_W1, sv_W2, sv_Wg, sv_Wv);
    ctx_kernel<<<64, HD>>>(ac, fWc);
    transpose_kernel<<<NTOK, 256>>>(emb);
    stageA_mma<<<dim3(NV, NTOK / TA), 256, SMEM_A>>>(sv_b1, sv_b2, sv_bg, sv_bv, sv_ls, sv_lb);
    stageB_kernel<<<NTOK / TM, 256, SMEM_B>>>(fWsk, fbsk, fW1, fb1, fW2, fb2,
                                              fWg, fbg, fWv, fbv, fls, flb, out_sw, out_sg);
    stageC_kernel<<<NTOK / 16, 256>>>(out_sw, out_tc);
}

// round 5
// speedup vs baseline: 2.7426x; 1.3565x over previous
#include <cuda_runtime.h>
#include <cuda_bf16.h>
#include <math.h>
#include <stdint.h>

#define NTOK 32768        // B*T
#define HD   160          // hidden = embed
#define NV   16           // variables
#define TA   64           // token tile (stage A + B)
#define PA2  84           // packed-A pitch (u32)  -> bank 20g+t, conflict-free
#define PB2  168          // packed-B pitch (u32)  -> bank 8t+g,  conflict-free
#define PAX  164          // fp32 skip pitch
#define CHUNK_U32 (2*16*PB2)   // 5376 u32: hi tile [16][168] then lo tile
#define PAB  20           // stage B big-A pitch (u32)
#define PBB  200          // stage B big-B pitch (u32)
#define CHUNKB 6400       // u32 per big-B chunk (hi 3200 + lo 3200)

static __device__ float g_embt[(size_t)NTOK * HD * NV];  // emb transposed [n][v][e]
static __device__ float g_ctx[64 * HD];                  // additional_context @ Wc
static __device__ __align__(16) uint32_t g_trh[(size_t)NTOK * NV * 80]; // transformed hi (bf16x2)
static __device__ __align__(16) uint32_t g_trl[(size_t)NTOK * NV * 80]; // transformed lo
static __device__ __align__(16) uint32_t g_wsplA[(size_t)16 * 4 * 5 * CHUNK_U32];
static __device__ __align__(16) uint32_t g_wsplB1[(size_t)80 * CHUNKB];  // fused W1|Wskip|pad
static __device__ __align__(16) uint32_t g_wsplB2[(size_t)5 * CHUNK_U32];

__device__ __forceinline__ float eluf(float x) { return x > 0.f ? x : expm1f(x); }
__device__ __forceinline__ float sigf(float x) { return 1.f / (1.f + expf(-x)); }

__device__ __forceinline__ uint32_t smem_u32(const void* p) {
    uint32_t a;
    asm("{ .reg .u64 t; cvta.to.shared.u64 t, %1; cvt.u32.u64 %0, t; }" : "=r"(a) : "l"(p));
    return a;
}
__device__ __forceinline__ void cp16(uint32_t saddr, const uint32_t* g) {
    asm volatile("cp.async.cg.shared.global [%0], [%1], 16;" :: "r"(saddr), "l"(g));
}
#define CP_COMMIT() asm volatile("cp.async.commit_group;" ::: "memory")
#define CP_WAIT1()  asm volatile("cp.async.wait_group 1;" ::: "memory")
#define CP_WAIT0()  asm volatile("cp.async.wait_group 0;" ::: "memory")

__device__ __forceinline__ void mma16(float* c, const uint32_t* a, const uint32_t* b) {
    asm volatile("mma.sync.aligned.m16n8k16.row.col.f32.bf16.bf16.f32 "
        "{%0,%1,%2,%3}, {%4,%5,%6,%7}, {%8,%9}, {%0,%1,%2,%3};"
        : "+f"(c[0]), "+f"(c[1]), "+f"(c[2]), "+f"(c[3])
        : "r"(a[0]), "r"(a[1]), "r"(a[2]), "r"(a[3]), "r"(b[0]), "r"(b[1]));
}

__device__ __forceinline__ void splitpack(float v0, float v1, uint32_t& hi, uint32_t& lo) {
    __nv_bfloat16 h0 = __float2bfloat16(v0), h1 = __float2bfloat16(v1);
    __nv_bfloat16 l0 = __float2bfloat16(v0 - __bfloat162float(h0));
    __nv_bfloat16 l1 = __float2bfloat16(v1 - __bfloat162float(h1));
    __nv_bfloat162 hh; hh.x = h0; hh.y = h1;
    __nv_bfloat162 ll; ll.x = l0; ll.y = l1;
    hi = *reinterpret_cast<uint32_t*>(&hh);
    lo = *reinterpret_cast<uint32_t*>(&ll);
}
__device__ __forceinline__ float2 unpk(uint32_t hi, uint32_t lo) {
    __nv_bfloat162 h = *reinterpret_cast<__nv_bfloat162*>(&hi);
    __nv_bfloat162 l = *reinterpret_cast<__nv_bfloat162*>(&lo);
    float2 r;
    r.x = __bfloat162float(h.x) + __bfloat162float(l.x);
    r.y = __bfloat162float(h.y) + __bfloat162float(l.y);
    return r;
}

// ===================== prep kernels =====================
__global__ void __launch_bounds__(256) prepA_kernel(
    const float* __restrict__ W1, const float* __restrict__ W2,
    const float* __restrict__ Wg, const float* __restrict__ Wv)
{
    int b = blockIdx.x;                 // v*20 + mat*5 + c
    int c = b % 5, mat = (b / 5) & 3, v = b / 20;
    const float* W = (mat == 0 ? W1 : mat == 1 ? W2 : mat == 2 ? Wg : Wv) + (size_t)v * HD * HD;
    uint32_t* dst = g_wsplA + (size_t)b * CHUNK_U32;
    for (int i = threadIdx.x; i < 16 * PB2; i += 256) {
        int pr = i / PB2, col = i - pr * PB2;
        float w0 = 0.f, w1 = 0.f;
        if (col < HD) {
            int k0 = c * 32 + 2 * pr;
            w0 = W[(size_t)k0 * HD + col];
            w1 = W[(size_t)(k0 + 1) * HD + col];
        }
        uint32_t hi, lo;
        splitpack(w0, w1, hi, lo);
        dst[i] = hi;
        dst[16 * PB2 + i] = lo;
    }
}

// fused big-B: rows = permuted flat k, cols: [0,160)=fW1, [160,176)=fWskip, [176,192)=0
__global__ void __launch_bounds__(256) prepB1_kernel(
    const float* __restrict__ W1, const float* __restrict__ Wsk)
{
    int c = blockIdx.x;                 // 80 chunks
    uint32_t* dst = g_wsplB1 + (size_t)c * CHUNKB;
    for (int i = threadIdx.x; i < 16 * PBB; i += 256) {
        int pr = i / PBB, col = i - pr * PBB;
        int k0 = c * 32 + 2 * pr, k1 = k0 + 1;
        int pk0 = (k0 % HD) * NV + (k0 / HD);
        int pk1 = (k1 % HD) * NV + (k1 / HD);
        float w0 = 0.f, w1 = 0.f;
        if (col < HD) {
            w0 = W1[(size_t)pk0 * HD + col];
            w1 = W1[(size_t)pk1 * HD + col];
        } else if (col < HD + NV) {
            w0 = Wsk[(size_t)pk0 * NV + (col - HD)];
            w1 = Wsk[(size_t)pk1 * NV + (col - HD)];
        }
        uint32_t hi, lo;
        splitpack(w0, w1, hi, lo);
        dst[i] = hi;
        dst[16 * PBB + i] = lo;
    }
}

__global__ void __launch_bounds__(256) prepB2_kernel(const float* __restrict__ W2) {
    int c = blockIdx.x;                 // 5 chunks
    uint32_t* dst = g_wsplB2 + (size_t)c * CHUNK_U32;
    for (int i = threadIdx.x; i < 16 * PB2; i += 256) {
        int pr = i / PB2, col = i - pr * PB2;
        float w0 = 0.f, w1 = 0.f;
        if (col < HD) {
            int k0 = c * 32 + 2 * pr;
            w0 = W2[(size_t)k0 * HD + col];
            w1 = W2[(size_t)(k0 + 1) * HD + col];
        }
        uint32_t hi, lo;
        splitpack(w0, w1, hi, lo);
        dst[i] = hi;
        dst[16 * PB2 + i] = lo;
    }
}

// ===================== shared mma machinery (N=160, K=160, PB2 pitch) =====================
extern __shared__ float smem[];

__device__ __forceinline__ void stage_chunk(uint32_t* sdst, const uint32_t* __restrict__ g, int tid) {
    uint32_t s = smem_u32(sdst);
#pragma unroll
    for (int i = 0; i < 5; ++i) {
        int q = i * 256 + tid;
        cp16(s + q * 16, g + q * 4);
    }
    int q = 1280 + tid;
    if (q < 1344) cp16(s + q * 16, g + q * 4);
}

__device__ __forceinline__ void loadB(const uint32_t* Bh, const uint32_t* Bl, int s,
                                      uint32_t bh[5][2], uint32_t bl[5][2],
                                      int g, int t, int n0w) {
#pragma unroll
    for (int f = 0; f < 5; ++f) {
        int nn = n0w + f * 8 + g;
        bh[f][0] = Bh[(s * 8 + t) * PB2 + nn];
        bh[f][1] = Bh[(s * 8 + 4 + t) * PB2 + nn];
        bl[f][0] = Bl[(s * 8 + t) * PB2 + nn];
        bl[f][1] = Bl[(s * 8 + 4 + t) * PB2 + nn];
    }
}

__device__ __forceinline__ void loadA(const uint32_t* s_Ah2, const uint32_t* s_Al2, int kp,
                                      uint32_t ah[2][4], uint32_t al[2][4],
                                      int g, int t, int m0w) {
#pragma unroll
    for (int mf = 0; mf < 2; ++mf) {
        int r0 = (m0w + mf * 16 + g) * PA2;
        int r1 = r0 + 8 * PA2;
        ah[mf][0] = s_Ah2[r0 + kp + t];     ah[mf][1] = s_Ah2[r1 + kp + t];
        ah[mf][2] = s_Ah2[r0 + kp + 4 + t]; ah[mf][3] = s_Al2 == s_Ah2 ? 0 : s_Ah2[r1 + kp + 4 + t];
        ah[mf][3] = s_Ah2[r1 + kp + 4 + t];
        al[mf][0] = s_Al2[r0 + kp + t];     al[mf][1] = s_Al2[r1 + kp + t];
        al[mf][2] = s_Al2[r0 + kp + 4 + t]; al[mf][3] = s_Al2[r1 + kp + 4 + t];
    }
}

__device__ __forceinline__ void mma_chunk(const uint32_t* sB, float acc[5][2][4],
                                          const uint32_t* s_Ah2, const uint32_t* s_Al2,
                                          int kp0, int g, int t, int m0w, int n0w) {
    const uint32_t* Bh = sB;
    const uint32_t* Bl = sB + 16 * PB2;
    uint32_t bh0[5][2], bl0[5][2], bh1[5][2], bl1[5][2];
    loadB(Bh, Bl, 0, bh0, bl0, g, t, n0w);

    uint32_t ah[2][4], al[2][4];
    loadA(s_Ah2, s_Al2, kp0, ah, al, g, t, m0w);
    loadB(Bh, Bl, 1, bh1, bl1, g, t, n0w);
#pragma unroll
    for (int f = 0; f < 5; ++f)
#pragma unroll
        for (int mf = 0; mf < 2; ++mf) {
            mma16(acc[f][mf], ah[mf], bh0[f]);
            mma16(acc[f][mf], ah[mf], bl0[f]);
            mma16(acc[f][mf], al[mf], bh0[f]);
        }
    loadA(s_Ah2, s_Al2, kp0 + 8, ah, al, g, t, m0w);
#pragma unroll
    for (int f = 0; f < 5; ++f)
#pragma unroll
        for (int mf = 0; mf < 2; ++mf) {
            mma16(acc[f][mf], ah[mf], bh1[f]);
            mma16(acc[f][mf], ah[mf], bl1[f]);
            mma16(acc[f][mf], al[mf], bh1[f]);
        }
}

__device__ __forceinline__ void gemm_bf16(const uint32_t* __restrict__ gW,
                                          const uint32_t* __restrict__ gWnext,
                                          uint32_t* sB0, uint32_t* sB1,
                                          float acc[5][2][4],
                                          const uint32_t* s_Ah2, const uint32_t* s_Al2,
                                          int par0, int tid, int g, int t, int m0w, int n0w) {
#pragma unroll 1
    for (int c = 0; c < 5; ++c) {
        uint32_t* cur = ((par0 + c) & 1) ? sB1 : sB0;
        uint32_t* nxt = ((par0 + c) & 1) ? sB0 : sB1;
        if (c < 4) {
            stage_chunk(nxt, gW + (size_t)(c + 1) * CHUNK_U32, tid);
            CP_COMMIT(); CP_WAIT1();
        } else if (gWnext) {
            stage_chunk(nxt, gWnext, tid);
            CP_COMMIT(); CP_WAIT1();
        } else {
            CP_WAIT0();
        }
        __syncthreads();
        mma_chunk(cur, acc, s_Ah2, s_Al2, c * 16, g, t, m0w, n0w);
        __syncthreads();
    }
}

#define ZERO_ACC5(acc) \
    _Pragma("unroll") for (int f = 0; f < 5; ++f) \
    _Pragma("unroll") for (int mf = 0; mf < 2; ++mf) \
    _Pragma("unroll") for (int r = 0; r < 4; ++r) acc[f][mf][r] = 0.f;
#define ZERO_ACC6(acc) \
    _Pragma("unroll") for (int f = 0; f < 6; ++f) \
    _Pragma("unroll") for (int mf = 0; mf < 2; ++mf) \
    _Pragma("unroll") for (int r = 0; r < 4; ++r) acc[f][mf][r] = 0.f;

// ===================== stage A =====================
__global__ void __launch_bounds__(256, 1) stageA_mma(
    const float* __restrict__ b1, const float* __restrict__ b2,
    const float* __restrict__ bg, const float* __restrict__ bv,
    const float* __restrict__ lns, const float* __restrict__ lnb)
{
    float* s_x    = smem;                      // [64][164] fp32 skip -> y
    float* s_bias = s_x + TA * PAX;            // 6*160
    float* s_red  = s_bias + 6 * HD;           // [64][2]
    uint32_t* s_Ah2 = (uint32_t*)(s_red + 128);
    uint32_t* s_Al2 = s_Ah2 + TA * PA2;
    uint32_t* sB0   = s_Al2 + TA * PA2;
    uint32_t* sB1   = sB0 + CHUNK_U32;

    const int v   = blockIdx.x;
    const int n0  = blockIdx.y * TA;
    const int tid = threadIdx.x;
    const int lane = tid & 31;
    const int wid  = tid >> 5;
    const int g = lane >> 2, t = lane & 3;
    const int m0w = (wid & 1) * 32;
    const int n0w = (wid >> 1) * 40;
    const int pib = n0w / 2;

    const uint32_t* wbase = g_wsplA + (size_t)v * 20 * CHUNK_U32;

    stage_chunk(sB0, wbase, tid);
    CP_COMMIT();

    for (int l = tid; l < HD; l += 256) {
        s_bias[l]          = b1[v * HD + l];
        s_bias[HD + l]     = b2[v * HD + l];
        s_bias[2*HD + l]   = bg[v * HD + l];
        s_bias[3*HD + l]   = bv[v * HD + l];
        s_bias[4*HD + l]   = lns[v * HD + l];
        s_bias[5*HD + l]   = lnb[v * HD + l];
    }

#pragma unroll
    for (int u = 0; u < 20; ++u) {
        int p = u * 256 + tid;
        int row = p / 80, pc = p - row * 80;
        float2 xv = *(const float2*)(g_embt + (size_t)(n0 + row) * (HD * NV) + (size_t)v * HD + 2 * pc);
        s_x[row * PAX + 2 * pc]     = xv.x;
        s_x[row * PAX + 2 * pc + 1] = xv.y;
        uint32_t hi, lo;
        splitpack(xv.x, xv.y, hi, lo);
        s_Ah2[row * PA2 + pc] = hi;
        s_Al2[row * PA2 + pc] = lo;
    }
    __syncthreads();

    float acc[5][2][4];

    // GEMM1: h1 = elu(x@W1 + b1)
    ZERO_ACC5(acc);
    gemm_bf16(wbase, wbase + 5 * CHUNK_U32, sB0, sB1, acc, s_Ah2, s_Al2, 0, tid, g, t, m0w, n0w);
#pragma unroll
    for (int f = 0; f < 5; ++f) {
        int col0 = n0w + f * 8 + 2 * t;
        int pi = pib + f * 4 + t;
#pragma unroll
        for (int mf = 0; mf < 2; ++mf) {
            int r0 = m0w + mf * 16 + g;
            float v00 = eluf(acc[f][mf][0] + s_bias[col0]);
            float v01 = eluf(acc[f][mf][1] + s_bias[col0 + 1]);
            float v10 = eluf(acc[f][mf][2] + s_bias[col0]);
            float v11 = eluf(acc[f][mf][3] + s_bias[col0 + 1]);
            splitpack(v00, v01, s_Ah2[r0 * PA2 + pi], s_Al2[r0 * PA2 + pi]);
            splitpack(v10, v11, s_Ah2[(r0 + 8) * PA2 + pi], s_Al2[(r0 + 8) * PA2 + pi]);
        }
    }

    // GEMM2: h2 = h1@W2 + b2
    ZERO_ACC5(acc);
    gemm_bf16(wbase + 5 * CHUNK_U32, wbase + 10 * CHUNK_U32, sB0, sB1, acc, s_Ah2, s_Al2, 1, tid, g, t, m0w, n0w);
#pragma unroll
    for (int f = 0; f < 5; ++f) {
        int col0 = n0w + f * 8 + 2 * t;
        int pi = pib + f * 4 + t;
#pragma unroll
        for (int mf = 0; mf < 2; ++mf) {
            int r0 = m0w + mf * 16 + g;
            float v00 = acc[f][mf][0] + s_bias[HD + col0];
            float v01 = acc[f][mf][1] + s_bias[HD + col0 + 1];
            float v10 = acc[f][mf][2] + s_bias[HD + col0];
            float v11 = acc[f][mf][3] + s_bias[HD + col0 + 1];
            splitpack(v00, v01, s_Ah2[r0 * PA2 + pi], s_Al2[r0 * PA2 + pi]);
            splitpack(v10, v11, s_Ah2[(r0 + 8) * PA2 + pi], s_Al2[(r0 + 8) * PA2 + pi]);
        }
    }

    // GEMM3: gate = sigmoid(h2@Wg + bg)
    ZERO_ACC5(acc);
    gemm_bf16(wbase + 10 * CHUNK_U32, wbase + 15 * CHUNK_U32, sB0, sB1, acc, s_Ah2, s_Al2, 0, tid, g, t, m0w, n0w);
    float gate[5][2][4];
#pragma unroll
    for (int f = 0; f < 5; ++f)
#pragma unroll
        for (int mf = 0; mf < 2; ++mf)
#pragma unroll
            for (int r = 0; r < 4; ++r) {
                int col = n0w + f * 8 + 2 * t + (r & 1);
                gate[f][mf][r] = sigf(acc[f][mf][r] + s_bias[2*HD + col]);
            }

    // GEMM4: y = x + gate*(h2@Wv + bv)
    ZERO_ACC5(acc);
    gemm_bf16(wbase + 15 * CHUNK_U32, (const uint32_t*)0, sB0, sB1, acc, s_Ah2, s_Al2, 1, tid, g, t, m0w, n0w);
#pragma unroll
    for (int f = 0; f < 5; ++f)
#pragma unroll
        for (int mf = 0; mf < 2; ++mf)
#pragma unroll
            for (int r = 0; r < 4; ++r) {
                int row = m0w + mf * 16 + g + (r >> 1) * 8;
                int col = n0w + f * 8 + 2 * t + (r & 1);
                float val = acc[f][mf][r] + s_bias[3*HD + col];
                s_x[row * PAX + col] = s_x[row * PAX + col] + gate[f][mf][r] * val;
            }
    __syncthreads();

#pragma unroll
    for (int rr = 0; rr < 8; ++rr) {
        int row = 8 * wid + rr;
        float s = 0.f, q = 0.f;
#pragma unroll
        for (int u = 0; u < 5; ++u) {
            float y = s_x[row * PAX + u * 32 + lane];
            s += y; q += y * y;
        }
#pragma unroll
        for (int off = 16; off; off >>= 1) {
            s += __shfl_xor_sync(0xffffffffu, s, off);
            q += __shfl_xor_sync(0xffffffffu, q, off);
        }
        if (lane == 0) {
            float mean = s * (1.f / HD);
            float var  = q * (1.f / HD) - mean * mean;
            s_red[row * 2]     = mean;
            s_red[row * 2 + 1] = rsqrtf(var + 1e-5f);
        }
    }
    __syncthreads();

    // normalized y -> packed bf16 hi/lo to g_trh/g_trl
#pragma unroll
    for (int u = 0; u < 20; ++u) {
        int p = u * 256 + tid;
        int row = p / 80, pc = p - row * 80;
        float mean = s_red[row * 2], rstd = s_red[row * 2 + 1];
        int j0 = 2 * pc, j1 = 2 * pc + 1;
        float y0 = (s_x[row * PAX + j0] - mean) * rstd * s_bias[4*HD + j0] + s_bias[5*HD + j0];
        float y1 = (s_x[row * PAX + j1] - mean) * rstd * s_bias[4*HD + j1] + s_bias[5*HD + j1];
        uint32_t hi, lo;
        splitpack(y0, y1, hi, lo);
        size_t base = (size_t)(n0 + row) * (NV * 80) + (size_t)v * 80 + pc;
        g_trh[base] = hi;
        g_trl[base] = lo;
    }
}

// ===================== transpose =====================
__global__ void __launch_bounds__(256) transpose_kernel(const float* __restrict__ emb) {
    __shared__ float s[HD * 17];
    size_t n = blockIdx.x;
    int tid = threadIdx.x;
    const float* src = emb + n * (HD * NV);
    for (int l = tid; l < HD * NV; l += 256) {
        int e = l >> 4, vv = l & 15;
        s[e * 17 + vv] = src[l];
    }
    __syncthreads();
    float* dst = g_embt + n * (HD * NV);
    for (int l = tid; l < HD * NV; l += 256) {
        int vv = l / HD, e = l - vv * HD;
        dst[l] = s[e * 17 + vv];
    }
}

__global__ void ctx_kernel(const float* __restrict__ ac, const float* __restrict__ Wc) {
    int b = blockIdx.x, j = threadIdx.x;
    float s = 0.f;
    for (int k = 0; k < HD; ++k)
        s = fmaf(ac[b * HD + k], Wc[k * HD + j], s);
    g_ctx[b * HD + j] = s;
}

// ===================== stage B (bf16 mma) =====================
__device__ __forceinline__ void stageB_chunk(uint32_t* dAh, uint32_t* dAl, uint32_t* dB,
                                             int n0, int c, int tid) {
    int r = tid >> 2, q = tid & 3;
    size_t abase = (size_t)(n0 + r) * (NV * 80) + (size_t)c * 16 + q * 4;
    cp16(smem_u32(dAh + r * PAB + q * 4), g_trh + abase);
    cp16(smem_u32(dAl + r * PAB + q * 4), g_trl + abase);
    const uint32_t* gsrc = g_wsplB1 + (size_t)c * CHUNKB;
    uint32_t db = smem_u32(dB);
#pragma unroll
    for (int i = 0; i < 7; ++i) {
        int idx = i * 256 + tid;
        if (idx < 1600) cp16(db + idx * 16, gsrc + idx * 4);
    }
}

__device__ __forceinline__ void mma_chunkB(const uint32_t* A_h, const uint32_t* A_l,
                                           const uint32_t* B, float acc[6][2][4],
                                           int g, int t, int m0w, int n0w48) {
    const uint32_t* Bh = B;
    const uint32_t* Bl = B + 16 * PBB;
#pragma unroll
    for (int s = 0; s < 2; ++s) {
        int kp = s * 8;
        uint32_t ah[2][4], al[2][4];
#pragma unroll
        for (int mf = 0; mf < 2; ++mf) {
            int r0 = (m0w + mf * 16 + g) * PAB;
            int r1 = r0 + 8 * PAB;
            ah[mf][0] = A_h[r0 + kp + t];     ah[mf][1] = A_h[r1 + kp + t];
            ah[mf][2] = A_h[r0 + kp + 4 + t]; ah[mf][3] = A_h[r1 + kp + 4 + t];
            al[mf][0] = A_l[r0 + kp + t];     al[mf][1] = A_l[r1 + kp + t];
            al[mf][2] = A_l[r0 + kp + 4 + t]; al[mf][3] = A_l[r1 + kp + 4 + t];
        }
#pragma unroll
        for (int f = 0; f < 6; ++f) {
            int nn = n0w48 + f * 8 + g;
            uint32_t bh[2], bl[2];
            bh[0] = Bh[(kp + t) * PBB + nn]; bh[1] = Bh[(kp + 4 + t) * PBB + nn];
            bl[0] = Bl[(kp + t) * PBB + nn]; bl[1] = Bl[(kp + 4 + t) * PBB + nn];
#pragma unroll
            for (int mf = 0; mf < 2; ++mf) {
                mma16(acc[f][mf], ah[mf], bh);
                mma16(acc[f][mf], ah[mf], bl);
                mma16(acc[f][mf], al[mf], bh);
            }
        }
    }
}

__global__ void __launch_bounds__(256, 1) stageB_mma(
    const float* __restrict__ b1,  const float* __restrict__ b2,
    const float* __restrict__ bsk, const float* __restrict__ bg,
    const float* __restrict__ bv,  const float* __restrict__ lns,
    const float* __restrict__ lnb, const float* __restrict__ Wg,
    const float* __restrict__ Wv,
    float* __restrict__ out_sw, float* __restrict__ out_sg)
{
    uint32_t* sm   = (uint32_t*)smem;
    uint32_t* bufr = sm;                       // 17920 u32 union region
    uint32_t* s_Ah2 = sm + 17920;              // [64][84]
    uint32_t* s_Al2 = s_Ah2 + TA * PA2;
    float* s_h3 = (float*)(s_Al2 + TA * PA2);  // [160][65] transposed
    float* s_sk = s_h3 + 160 * 65;             // [64][16]
    float* s_gv = s_sk + TA * NV;              // [160][32]
    float* s_cb = s_gv + HD * 32;              // 400 floats

    uint32_t* sAh[2] = { bufr,        bufr + 2560 };
    uint32_t* sAl[2] = { bufr + 1280, bufr + 3840 };
    uint32_t* sBB[2] = { bufr + 5120, bufr + 5120 + CHUNKB };
    uint32_t* sB20 = bufr;                     // GEMM2 buffers alias big region
    uint32_t* sB21 = bufr + CHUNK_U32;

    const int n0  = blockIdx.x * TA;
    const int tid = threadIdx.x;
    const int lane = tid & 31;
    const int wid  = tid >> 5;
    const int g = lane >> 2, t = lane & 3;
    const int m0w   = (wid & 1) * 32;
    const int n0w48 = (wid >> 1) * 48;
    const int n0w40 = (wid >> 1) * 40;
    const int bidx  = n0 >> 9;

    stageB_chunk(sAh[0], sAl[0], sBB[0], n0, 0, tid);
    CP_COMMIT();

    if (tid < HD) {
        s_cb[tid]       = b1[tid] + g_ctx[bidx * HD + tid];
        s_cb[HD + tid]  = b2[tid];
    }
    if (tid < NV) {
        s_cb[320 + tid] = bg[tid];
        s_cb[336 + tid] = bv[tid];
        s_cb[352 + tid] = lns[tid];
        s_cb[368 + tid] = lnb[tid];
        s_cb[384 + tid] = bsk[tid];
    }
    // fused Wg|Wv [160][32]
#pragma unroll
    for (int u = 0; u < 20; ++u) {
        int l = u * 256 + tid;
        int cc = l & 31, k = l >> 5;
        s_gv[k * 32 + cc] = (cc < NV) ? Wg[k * NV + cc] : Wv[k * NV + (cc - NV)];
    }

    float acc[6][2][4];
    ZERO_ACC6(acc);

    // ---- big GEMM: [64 x 2560] @ [2560 x 192] ----
#pragma unroll 1
    for (int c = 0; c < 80; ++c) {
        int cur = c & 1, nxt = cur ^ 1;
        if (c < 79) {
            stageB_chunk(sAh[nxt], sAl[nxt], sBB[nxt], n0, c + 1, tid);
            CP_COMMIT(); CP_WAIT1();
        } else {
            CP_WAIT0();
        }
        __syncthreads();
        mma_chunkB(sAh[cur], sAl[cur], sBB[cur], acc, g, t, m0w, n0w48);
        __syncthreads();
    }

    // epilogue: cols<160 -> h2 (elu, split-pack); 160..175 -> skip
#pragma unroll
    for (int f = 0; f < 6; ++f) {
        int col0 = n0w48 + f * 8 + 2 * t;
#pragma unroll
        for (int mf = 0; mf < 2; ++mf) {
            int r0 = m0w + mf * 16 + g;
            float v00 = acc[f][mf][0], v01 = acc[f][mf][1];
            float v10 = acc[f][mf][2], v11 = acc[f][mf][3];
            if (col0 < HD) {
                int pi = col0 >> 1;
                float e00 = eluf(v00 + s_cb[col0]);
                float e01 = eluf(v01 + s_cb[col0 + 1]);
                float e10 = eluf(v10 + s_cb[col0]);
                float e11 = eluf(v11 + s_cb[col0 + 1]);
                splitpack(e00, e01, s_Ah2[r0 * PA2 + pi], s_Al2[r0 * PA2 + pi]);
                splitpack(e10, e11, s_Ah2[(r0 + 8) * PA2 + pi], s_Al2[(r0 + 8) * PA2 + pi]);
            } else if (col0 < HD + NV) {
                int sc = col0 - HD;
                s_sk[r0 * NV + sc]       = v00;
                s_sk[r0 * NV + sc + 1]   = v01;
                s_sk[(r0 + 8) * NV + sc]     = v10;
                s_sk[(r0 + 8) * NV + sc + 1] = v11;
            }
        }
    }
    __syncthreads();

    // prestage GEMM2 chunk 0 (buffers alias big region; all mma done)
    stage_chunk(sB20, g_wsplB2, tid);
    CP_COMMIT();
    __syncthreads();

    // ---- GEMM2: h3 = h2 @ W2 + b2 ----
    float acc5[5][2][4];
    ZERO_ACC5(acc5);
    gemm_bf16(g_wsplB2, (const uint32_t*)0, sB20, sB21, acc5, s_Ah2, s_Al2, 0, tid, g, t, m0w, n0w40);
#pragma unroll
    for (int f = 0; f < 5; ++f)
#pragma unroll
        for (int mf = 0; mf < 2; ++mf)
#pragma unroll
            for (int r = 0; r < 4; ++r) {
                int row = m0w + mf * 16 + g + (r >> 1) * 8;
                int col = n0w40 + f * 8 + 2 * t + (r & 1);
                s_h3[col * 65 + row] = acc5[f][mf][r] + s_cb[HD + col];
            }
    __syncthreads();

    // ---- gv GEMM: lane c<16 gate col, c>=16 value col ----
    float gv[8];
#pragma unroll
    for (int rr = 0; rr < 8; ++rr) gv[rr] = 0.f;
    const int c = lane;
#pragma unroll 4
    for (int k = 0; k < HD; ++k) {
        float w = s_gv[k * 32 + c];
        const float* h3k = s_h3 + k * 65 + 8 * wid;
#pragma unroll
        for (int rr = 0; rr < 8; ++rr)
            gv[rr] = fmaf(h3k[rr], w, gv[rr]);
    }

    int vc = c & 15;
    float bgv = (c < NV) ? s_cb[320 + vc] : s_cb[336 + vc];
    float skb = s_cb[384 + vc];
    float lsc = s_cb[352 + vc], lbc = s_cb[368 + vc];
#pragma unroll
    for (int rr = 0; rr < 8; ++rr) {
        int row = 8 * wid + rr;
        float z = gv[rr] + bgv;
        float gval = (c < NV) ? sigf(z) : z;
        float partner = __shfl_xor_sync(0xffffffffu, gval, 16);
        float y = s_sk[row * NV + vc] + skb + gval * partner;
        float s = y, q = y * y;
#pragma unroll
        for (int off = 8; off; off >>= 1) {
            s += __shfl_xor_sync(0xffffffffu, s, off);
            q += __shfl_xor_sync(0xffffffffu, q, off);
        }
        float mean = s * (1.f / 16.f);
        float var  = q * (1.f / 16.f) - mean * mean;
        float rstd = rsqrtf(var + 1e-5f);
        float logit = (y - mean) * rstd * lsc + lbc;
        float mx = logit;
#pragma unroll
        for (int off = 8; off; off >>= 1)
            mx = fmaxf(mx, __shfl_xor_sync(0xffffffffu, mx, off));
        float e = expf(logit - mx);
        float se = e;
#pragma unroll
        for (int off = 8; off; off >>= 1)
            se += __shfl_xor_sync(0xffffffffu, se, off);
        if (c < NV) {
            int n = n0 + row;
            out_sw[(size_t)n * NV + c] = e / se;
            out_sg[(size_t)n * NV + c] = gval;
        }
    }
}

// ===================== stage C =====================
__global__ void __launch_bounds__(256) stageC_kernel(const float* __restrict__ sw,
                                                     float* __restrict__ out_tc) {
    __shared__ float s_w[16 * NV];
    int n0 = blockIdx.x * 16;
    int tid = threadIdx.x;
    s_w[tid] = sw[(size_t)n0 * NV + tid];
    __syncthreads();
#pragma unroll
    for (int u = 0; u < 5; ++u) {
        int l = u * 256 + tid;                 // 16 tokens * 80 pairs
        int m = l / 80, pc = l - m * 80;
        size_t base = (size_t)(n0 + m) * (NV * 80) + pc;
        float a0 = 0.f, a1 = 0.f;
#pragma unroll
        for (int vv = 0; vv < NV; ++vv) {
            float2 x = unpk(g_trh[base + vv * 80], g_trl[base + vv * 80]);
            float w = s_w[m * NV + vv];
            a0 = fmaf(x.x, w, a0);
            a1 = fmaf(x.y, w, a1);
        }
        float* dst = out_tc + (size_t)(n0 + m) * HD + 2 * pc;
        dst[0] = a0;
        dst[1] = a1;
    }
}

// ===================== launch =====================
extern "C" void kernel_launch(void* const* d_in, const int* in_sizes, int n_in,
                              void* d_out, int out_size)
{
    const float* emb   = (const float*)d_in[0];
    const float* ac    = (const float*)d_in[1];
    const float* sv_W1 = (const float*)d_in[2];
    const float* sv_b1 = (const float*)d_in[3];
    const float* sv_W2 = (const float*)d_in[4];
    const float* sv_b2 = (const float*)d_in[5];
    const float* sv_Wg = (const float*)d_in[6];
    const float* sv_bg = (const float*)d_in[7];
    const float* sv_Wv = (const float*)d_in[8];
    const float* sv_bv = (const float*)d_in[9];
    const float* sv_ls = (const float*)d_in[10];
    const float* sv_lb = (const float*)d_in[11];
    const float* fWsk  = (const float*)d_in[12];
    const float* fbsk  = (const float*)d_in[13];
    const float* fW1   = (const float*)d_in[14];
    const float* fb1   = (const float*)d_in[15];
    const float* fWc   = (const float*)d_in[16];
    const float* fW2   = (const float*)d_in[17];
    const float* fb2   = (const float*)d_in[18];
    const float* fWg   = (const float*)d_in[19];
    const float* fbg   = (const float*)d_in[20];
    const float* fWv   = (const float*)d_in[21];
    const float* fbv   = (const float*)d_in[22];
    const float* fls   = (const float*)d_in[23];
    const float* flb   = (const float*)d_in[24];

    float* out    = (float*)d_out;
    float* out_tc = out;
    float* out_sw = out + (size_t)NTOK * HD;
    float* out_sg = out_sw + (size_t)NTOK * NV;

    const int SMEM_A = (TA * PAX + 6 * HD + 128) * 4 + (2 * TA * PA2 + 2 * CHUNK_U32) * 4;
    const int SMEM_B = (17920 + 2 * TA * PA2) * 4 + (160 * 65 + TA * NV + HD * 32 + 400) * 4; // 182464
    cudaFuncSetAttribute(stageA_mma, cudaFuncAttributeMaxDynamicSharedMemorySize, SMEM_A);
    cudaFuncSetAttribute(stageB_mma, cudaFuncAttributeMaxDynamicSharedMemorySize, SMEM_B);

    prepA_kernel<<<320, 256>>>(sv_W1, sv_W2, sv_Wg, sv_Wv);
    prepB1_kernel<<<80, 256>>>(fW1, fWsk);
    prepB2_kernel<<<5, 256>>>(fW2);
    ctx_kernel<<<64, HD>>>(ac, fWc);
    transpose_kernel<<<NTOK, 256>>>(emb);
    stageA_mma<<<dim3(NV, NTOK / TA), 256, SMEM_A>>>(sv_b1, sv_b2, sv_bg, sv_bv, sv_ls, sv_lb);
    stageB_mma<<<NTOK / TA, 256, SMEM_B>>>(fb1, fb2, fbsk, fbg, fbv, fls, flb,
                                           fWg, fWv, out_sw, out_sg);
    stageC_kernel<<<NTOK / 16, 256>>>(out_sw, out_tc);
}